// round 9
// baseline (speedup 1.0000x reference)
#include <cuda_runtime.h>
#include <math.h>

// ---------------- problem constants ----------------
#define NN    50000
#define FIN   256
#define FOUT  128
#define HH    128
#define DD    16
#define EE    (NN*DD)     // 800000
#define G4    512         // 4*H

// ---------------- scratch ----------------
__device__ float    g_proj[(size_t)NN*FOUT];   // 25.6MB
__device__ float    g_P2[(size_t)NN*G4];       // 102.4MB  P2 = proj @ w_ih^T (permuted cols)
__device__ float    g_ssrc[NN];
__device__ float    g_strg[NN];
__device__ float    g_scores[EE];
__device__ unsigned g_gmax;
__device__ int      g_seqsrc[EE];
__device__ float    g_seqatt[EE];
__device__ float    g_wih_p[G4*HH];            // permuted w_ih  [512 rows][128 k]  (row-major)
__device__ float    g_whh_pT[HH*G4];           // permuted w_hh  [128 k][512 cols]  (K-MAJOR)
__device__ float    g_bcat[G4];

// ---------------- helpers ----------------
__device__ __forceinline__ unsigned fenc(float f) {
    unsigned i = __float_as_uint(f);
    return (i & 0x80000000u) ? ~i : (i | 0x80000000u);
}
__device__ __forceinline__ float fdec(unsigned u) {
    return (u & 0x80000000u) ? __uint_as_float(u ^ 0x80000000u) : __uint_as_float(~u);
}
__device__ __forceinline__ float tanh_fast(float x) {
    float r;
    asm("tanh.approx.f32 %0, %1;" : "=f"(r) : "f"(x));
    return r;
}
__device__ __forceinline__ float sig_fast(float x) {
    return fmaf(tanh_fast(0.5f * x), 0.5f, 0.5f);
}
// packed f32x2 ops (Blackwell sm_103a)
typedef unsigned long long ull;
__device__ __forceinline__ ull pack2(float x, float y) {
    ull r; asm("mov.b64 %0, {%1,%2};" : "=l"(r) : "f"(x), "f"(y)); return r;
}
__device__ __forceinline__ float2 unpack2(ull v) {
    float2 r; asm("mov.b64 {%0,%1}, %2;" : "=f"(r.x), "=f"(r.y) : "l"(v)); return r;
}
__device__ __forceinline__ ull ffma2_(ull a, ull b, ull c) {
    ull d; asm("fma.rn.f32x2 %0, %1, %2, %3;" : "=l"(d) : "l"(a), "l"(b), "l"(c)); return d;
}
__device__ __forceinline__ ull add2_(ull a, ull b) {
    ull d; asm("add.rn.f32x2 %0, %1, %2;" : "=l"(d) : "l"(a), "l"(b)); return d;
}
// cp.async helpers
__device__ __forceinline__ void cp16(unsigned dst, const void* src) {
    asm volatile("cp.async.ca.shared.global [%0], [%1], 16;" :: "r"(dst), "l"(src));
}
__device__ __forceinline__ void cp_commit() { asm volatile("cp.async.commit_group;"); }
template <int N>
__device__ __forceinline__ void cp_wait() { asm volatile("cp.async.wait_group %0;" :: "n"(N)); }

// ---------------- kernel: build permuted weights ----------------
__global__ void prep_w_k(const float* __restrict__ wih, const float* __restrict__ whh,
                         const float* __restrict__ bih, const float* __restrict__ bhh) {
    int idx = blockIdx.x * blockDim.x + threadIdx.x;   // 0..65535
    int R = idx >> 7;
    int k = idx & 127;
    int ch = R >> 7, c = R & 127;
    int gate = c >> 5, dd = c & 31;
    int grow = gate * 128 + ch * 32 + dd;
    g_wih_p[R * 128 + k]  = wih[grow * 128 + k];
    g_whh_pT[k * 512 + R] = whh[grow * 128 + k];
    if (k == 0) g_bcat[R] = bih[grow] + bhh[grow];
}

// ---------------- kernel: proj + skip fused GEMM (FFMA2, row-paired) ----------------
__global__ __launch_bounds__(256) void gemm1_k(const float* __restrict__ x,
                                               const float* __restrict__ Wp,
                                               const float* __restrict__ Wsk,
                                               float* __restrict__ out) {
    __shared__ float xs2[32 * 66];    // [kk][row] transposed, pad 2
    __shared__ float ws[256 * 33];    // [col][kk]
    int tid = threadIdx.x, lane = tid & 31, wrp = tid >> 5;
    int n0 = blockIdx.x * 64;
    ull accp[4][8];
#pragma unroll
    for (int rp = 0; rp < 4; rp++)
#pragma unroll
        for (int j = 0; j < 8; j++) accp[rp][j] = 0ull;

    for (int k0 = 0; k0 < 256; k0 += 32) {
        __syncthreads();
#pragma unroll
        for (int v = 0; v < 8; v++) {
            int idx = tid + v * 256;
            int r = idx >> 5, kk = idx & 31;
            int n = n0 + r;
            xs2[kk * 66 + r] = (n < NN) ? x[(size_t)n * 256 + k0 + kk] : 0.0f;
        }
#pragma unroll
        for (int v = 0; v < 32; v++) {
            int idx = tid + v * 256;
            int c = idx >> 5, kk = idx & 31;
            ws[c * 33 + kk] = (c < 128) ? Wp[c * 256 + k0 + kk]
                                        : Wsk[(c - 128) * 256 + k0 + kk];
        }
        __syncthreads();
#pragma unroll 4
        for (int kk = 0; kk < 32; kk++) {
            ull uvp[4], wvp[8];
#pragma unroll
            for (int rp = 0; rp < 4; rp++) {
                float2 u2 = *(const float2*)(xs2 + kk * 66 + wrp * 8 + 2 * rp);
                uvp[rp] = pack2(u2.x, u2.y);
            }
#pragma unroll
            for (int j = 0; j < 8; j++) {
                float wv = ws[(j * 32 + lane) * 33 + kk];
                wvp[j] = pack2(wv, wv);
            }
#pragma unroll
            for (int rp = 0; rp < 4; rp++)
#pragma unroll
                for (int j = 0; j < 8; j++)
                    accp[rp][j] = ffma2_(uvp[rp], wvp[j], accp[rp][j]);
        }
    }
#pragma unroll
    for (int rp = 0; rp < 4; rp++) {
        int n = n0 + wrp * 8 + 2 * rp;
#pragma unroll
        for (int j = 0; j < 8; j++) {
            float2 res = unpack2(accp[rp][j]);
            int c = j * 32 + lane;
            if (n < NN) {
                if (c < 128) g_proj[(size_t)n * 128 + c] = res.x;
                else         out[(size_t)n * 128 + (c - 128)] = res.x;
            }
            if (n + 1 < NN) {
                if (c < 128) g_proj[(size_t)(n + 1) * 128 + c] = res.y;
                else         out[(size_t)(n + 1) * 128 + (c - 128)] = res.y;
            }
        }
    }
}

// ---------------- kernel: P2 = proj @ w_ih_p^T (FFMA2, row-paired) ----------
__global__ __launch_bounds__(256) void p2_k() {
    __shared__ float xs2[32 * 66];
    __shared__ float ws[256 * 33];
    int tid = threadIdx.x, lane = tid & 31, wrp = tid >> 5;
    int n0 = blockIdx.x * 64;
    int coff = blockIdx.y * 256;
    ull accp[4][8];
#pragma unroll
    for (int rp = 0; rp < 4; rp++)
#pragma unroll
        for (int j = 0; j < 8; j++) accp[rp][j] = 0ull;

    for (int k0 = 0; k0 < 128; k0 += 32) {
        __syncthreads();
#pragma unroll
        for (int v = 0; v < 8; v++) {
            int idx = tid + v * 256;
            int r = idx >> 5, kk = idx & 31;
            int n = n0 + r;
            xs2[kk * 66 + r] = (n < NN) ? g_proj[(size_t)n * 128 + k0 + kk] : 0.0f;
        }
#pragma unroll
        for (int v = 0; v < 32; v++) {
            int idx = tid + v * 256;
            int c = idx >> 5, kk = idx & 31;
            ws[c * 33 + kk] = g_wih_p[(coff + c) * 128 + k0 + kk];
        }
        __syncthreads();
#pragma unroll 4
        for (int kk = 0; kk < 32; kk++) {
            ull uvp[4], wvp[8];
#pragma unroll
            for (int rp = 0; rp < 4; rp++) {
                float2 u2 = *(const float2*)(xs2 + kk * 66 + wrp * 8 + 2 * rp);
                uvp[rp] = pack2(u2.x, u2.y);
            }
#pragma unroll
            for (int j = 0; j < 8; j++) {
                float wv = ws[(j * 32 + lane) * 33 + kk];
                wvp[j] = pack2(wv, wv);
            }
#pragma unroll
            for (int rp = 0; rp < 4; rp++)
#pragma unroll
                for (int j = 0; j < 8; j++)
                    accp[rp][j] = ffma2_(uvp[rp], wvp[j], accp[rp][j]);
        }
    }
#pragma unroll
    for (int rp = 0; rp < 4; rp++) {
        int n = n0 + wrp * 8 + 2 * rp;
#pragma unroll
        for (int j = 0; j < 8; j++) {
            float2 res = unpack2(accp[rp][j]);
            int c = coff + j * 32 + lane;
            if (n < NN)     g_P2[(size_t)n * 512 + c] = res.x;
            if (n + 1 < NN) g_P2[(size_t)(n + 1) * 512 + c] = res.y;
        }
    }
}

// ---------------- kernel: per-node attention dots ----------------
__global__ void sdots_k(const float* __restrict__ as, const float* __restrict__ at) {
    int gtid = blockIdx.x * blockDim.x + threadIdx.x;
    int warp = gtid >> 5;
    int lane = gtid & 31;
    if (warp >= NN) return;
    const float* p = g_proj + (size_t)warp * 128;
    float s1 = 0.0f, s2 = 0.0f;
#pragma unroll
    for (int d = lane; d < 128; d += 32) {
        float v = p[d];
        s1 = fmaf(v, as[d], s1);
        s2 = fmaf(v, at[d], s2);
    }
#pragma unroll
    for (int o = 16; o; o >>= 1) {
        s1 += __shfl_xor_sync(0xffffffffu, s1, o);
        s2 += __shfl_xor_sync(0xffffffffu, s2, o);
    }
    if (lane == 0) { g_ssrc[warp] = s1; g_strg[warp] = s2; }
}

__global__ void initmax_k() { g_gmax = 0u; }

// ---------------- kernel: edge scores + global max ----------------
__global__ void scores_k(const int* __restrict__ ei) {
    int e = blockIdx.x * blockDim.x + threadIdx.x;
    int s = ei[e];
    int t = ei[EE + e];
    float sc = g_ssrc[s] + g_strg[t];
    sc = (sc >= 0.0f) ? sc : 0.2f * sc;
    g_scores[e] = sc;
    float m = sc;
#pragma unroll
    for (int o = 16; o; o >>= 1) m = fmaxf(m, __shfl_xor_sync(0xffffffffu, m, o));
    __shared__ float wm[8];
    int lane = threadIdx.x & 31, wid = threadIdx.x >> 5;
    if (lane == 0) wm[wid] = m;
    __syncthreads();
    if (threadIdx.x == 0) {
        float mm = wm[0];
#pragma unroll
        for (int w = 1; w < 8; w++) mm = fmaxf(mm, wm[w]);
        atomicMax(&g_gmax, fenc(mm));
    }
}

// ---------------- kernel: softmax + stable sort ----------------
__global__ void sort_k(const int* __restrict__ ei) {
    int n = blockIdx.x * blockDim.x + threadIdx.x;
    if (n >= NN) return;
    float gmax = fdec(g_gmax);
    float ev[DD], srt[DD];
    int idx[DD];
    float denom = 0.0f;
#pragma unroll
    for (int j = 0; j < DD; j++) {
        float e = expf(g_scores[n * DD + j] - gmax);
        ev[j] = e;
        denom += e;
    }
    denom += 1e-16f;
    for (int j = 0; j < DD; j++) {
        float key = ev[j];
        int pos = j;
        while (pos > 0 && srt[pos - 1] <= key) {
            srt[pos] = srt[pos - 1];
            idx[pos] = idx[pos - 1];
            pos--;
        }
        srt[pos] = key;
        idx[pos] = j;
    }
    float inv = 1.0f / denom;
#pragma unroll
    for (int t = 0; t < DD; t++) {
        int j = idx[t];
        g_seqsrc[n * DD + t] = ei[n * DD + j];
        g_seqatt[n * DD + t] = srt[t] * inv;
    }
}

// ---------------- kernel: backward LSTM, FFMA2, duplicated-h, MOV-free loop ----
// 64 nodes / block, 256 threads (8 warps). Warp owns 8 rows; lane (hl=lane>>4,
// p=lane&15) owns hidden-dim pairs {2p,2p+1} of chunks (hl) and (hl+2).
// h stored DUPLICATED in SMEM ([row][k][2]) so the (h,h) FFMA2 operand is one
// broadcast LDS.64; weight pairs load directly as 64-bit. c in registers.
#define U2_STR 264
#define KT 32
#define W_STR 520
#define LSTM_SM_FLOATS (64*U2_STR + 2*KT*W_STR + 160)

__global__ __launch_bounds__(256, 1) void lstm_k(const float* __restrict__ bias,
                                                 float* __restrict__ out) {
    extern __shared__ float sm[];
    float* u    = sm;                          // [64][U2_STR] duplicated h (in-place)
    float* wsm  = sm + 64 * U2_STR;            // [2][KT][W_STR] w tiles
    float* satt = wsm + 2 * KT * W_STR;        // [64]
    int*   ssrc = (int*)(satt + 64);           // [64]

    int tid = threadIdx.x, lane = tid & 31, wrp = tid >> 5;
    int hl = lane >> 4, p = lane & 15;
    int n0 = blockIdx.x * 64;
    unsigned wsm_s = (unsigned)__cvta_generic_to_shared(wsm);

    // col offsets: jj = cs*4 + g -> col = (hl+2cs)*128 + g*32 + 2p
    int co[8];
#pragma unroll
    for (int jj = 0; jj < 8; jj++)
        co[jj] = (hl + 2 * (jj >> 2)) * 128 + (jj & 3) * 32 + 2 * p;

    // bias pairs
    ull bcp[8];
#pragma unroll
    for (int jj = 0; jj < 8; jj++) {
        float2 b2 = *(const float2*)(g_bcat + co[jj]);
        bcp[jj] = pack2(b2.x, b2.y);
    }

    // cell state: creg2[row][cs] = c for dims (hl+2cs)*32 + {2p,2p+1}
    float2 creg2[8][2];
#pragma unroll
    for (int i = 0; i < 8; i++)
#pragma unroll
        for (int cs = 0; cs < 2; cs++) creg2[i][cs] = make_float2(0.0f, 0.0f);

    // zero duplicated-h buffer (64*264 = 16896 = 66*256 exact)
    for (int idx = tid; idx < 64 * U2_STR; idx += 256) u[idx] = 0.0f;
    __syncthreads();

#pragma unroll 1
    for (int t = 0; t < DD; t++) {
        if (tid < 64) {
            int n = n0 + tid;
            if (n < NN) {
                ssrc[tid] = g_seqsrc[n * DD + t];
                satt[tid] = g_seqatt[n * DD + t];
            } else {
                ssrc[tid] = 0;
                satt[tid] = 0.0f;
            }
        }
        __syncthreads();

        ull accp[8][8];
#pragma unroll
        for (int i = 0; i < 8; i++)
#pragma unroll
            for (int jj = 0; jj < 8; jj++) accp[i][jj] = 0ull;

        if (t > 0) {
            // prologue: stage tile 0 (k 0..31) into buffer 0
#pragma unroll
            for (int v = 0; v < 16; v++) {
                int f4 = tid + v * 256;
                int kk = f4 >> 7, c4 = f4 & 127;
                cp16(wsm_s + (kk * W_STR + c4 * 4) * 4,
                     g_whh_pT + (size_t)kk * 512 + c4 * 4);
            }
            cp_commit();

#pragma unroll 1
            for (int kt = 0; kt < 4; kt++) {
                if (kt < 3) {
                    unsigned db = wsm_s + (((kt + 1) & 1) * KT * W_STR) * 4;
#pragma unroll
                    for (int v = 0; v < 16; v++) {
                        int f4 = tid + v * 256;
                        int kk = f4 >> 7, c4 = f4 & 127;
                        cp16(db + (kk * W_STR + c4 * 4) * 4,
                             g_whh_pT + (size_t)((kt + 1) * KT + kk) * 512 + c4 * 4);
                    }
                    cp_commit();
                    cp_wait<1>();
                } else {
                    cp_wait<0>();
                }
                __syncthreads();

                const float* wb  = wsm + (kt & 1) * KT * W_STR;
                const float* ubd = u + kt * KT * 2;
#pragma unroll 4
                for (int kk = 0; kk < KT; kk++) {
                    ull up[8], wvp[8];
#pragma unroll
                    for (int i = 0; i < 8; i++)
                        up[i] = *(const ull*)(ubd + (wrp * 8 + i) * U2_STR + 2 * kk);
#pragma unroll
                    for (int jj = 0; jj < 8; jj++)
                        wvp[jj] = *(const ull*)(wb + kk * W_STR + co[jj]);
#pragma unroll
                    for (int i = 0; i < 8; i++)
#pragma unroll
                        for (int jj = 0; jj < 8; jj++)
                            accp[i][jj] = ffma2_(up[i], wvp[jj], accp[i][jj]);
                }
                __syncthreads();
            }
        }

        // x-contribution: acc = acc + bias + att * P2[src]  (batched 2 rows)
#pragma unroll
        for (int b = 0; b < 4; b++) {
            ull pvp[2][8];
#pragma unroll
            for (int i2 = 0; i2 < 2; i2++) {
                int s = ssrc[wrp * 8 + b * 2 + i2];
                const float* pp = g_P2 + (size_t)s * 512;
#pragma unroll
                for (int jj = 0; jj < 8; jj++)
                    pvp[i2][jj] = *(const ull*)(pp + co[jj]);
            }
#pragma unroll
            for (int i2 = 0; i2 < 2; i2++) {
                int i = b * 2 + i2;
                float a = satt[wrp * 8 + i];
                ull ap = pack2(a, a);
#pragma unroll
                for (int jj = 0; jj < 8; jj++)
                    accp[i][jj] = ffma2_(ap, pvp[i2][jj], add2_(accp[i][jj], bcp[jj]));
            }
        }

        // gate activations + c/h update (duplicated h written as one STS.128)
#pragma unroll
        for (int i = 0; i < 8; i++) {
#pragma unroll
            for (int cs = 0; cs < 2; cs++) {
                float2 iv = unpack2(accp[i][cs * 4 + 0]);
                float2 fv = unpack2(accp[i][cs * 4 + 1]);
                float2 gv = unpack2(accp[i][cs * 4 + 2]);
                float2 ov = unpack2(accp[i][cs * 4 + 3]);
                float2 cp2 = creg2[i][cs];
                float c0 = fmaf(sig_fast(fv.x), cp2.x, sig_fast(iv.x) * tanh_fast(gv.x));
                float c1 = fmaf(sig_fast(fv.y), cp2.y, sig_fast(iv.y) * tanh_fast(gv.y));
                creg2[i][cs] = make_float2(c0, c1);
                float h0 = sig_fast(ov.x) * tanh_fast(c0);
                float h1 = sig_fast(ov.y) * tanh_fast(c1);
                int dbase = ((hl + 2 * cs) * 32 + 2 * p) * 2;
                *(float4*)(u + (wrp * 8 + i) * U2_STR + dbase) =
                    make_float4(h0, h0, h1, h1);
            }
        }
        __syncthreads();
    }

    // epilogue: final h in u (duplicated layout, read .x copy)
    for (int idx = tid; idx < 64 * 128; idx += 256) {
        int r = idx >> 7, d = idx & 127;
        int n = n0 + r;
        if (n < NN) {
            float v = u[r * U2_STR + 2 * d] + out[(size_t)n * 128 + d] + bias[d];
            out[(size_t)n * 128 + d] = (v >= 0.0f) ? v : 0.01f * v;
        }
    }
}

// ---------------- launch ----------------
extern "C" void kernel_launch(void* const* d_in, const int* in_sizes, int n_in,
                              void* d_out, int out_size) {
    const float* x    = (const float*)d_in[0];
    const float* Wp   = (const float*)d_in[1];
    const float* asrc = (const float*)d_in[2];
    const float* atrg = (const float*)d_in[3];
    const float* Wsk  = (const float*)d_in[4];
    const float* bias = (const float*)d_in[5];
    // d_in[6..9]: forward-direction weights, unused by the reference
    const float* wihb = (const float*)d_in[10];
    const float* whhb = (const float*)d_in[11];
    const float* bihb = (const float*)d_in[12];
    const float* bhhb = (const float*)d_in[13];
    const int*   ei   = (const int*)d_in[14];
    float* out = (float*)d_out;

    (void)in_sizes; (void)n_in; (void)out_size;

    cudaFuncSetAttribute(lstm_k, cudaFuncAttributeMaxDynamicSharedMemorySize,
                         LSTM_SM_FLOATS * (int)sizeof(float));

    prep_w_k<<<256, 256>>>(wihb, whhb, bihb, bhhb);
    gemm1_k<<<(NN + 63) / 64, 256>>>(x, Wp, Wsk, out);
    {
        dim3 g((NN + 63) / 64, 2);
        p2_k<<<g, 256>>>();
    }
    sdots_k<<<(NN * 32 + 255) / 256, 256>>>(asrc, atrg);
    initmax_k<<<1, 1>>>();
    scores_k<<<EE / 256, 256>>>(ei);
    sort_k<<<(NN + 255) / 256, 256>>>(ei);
    lstm_k<<<(NN + 63) / 64, 256, LSTM_SM_FLOATS * (int)sizeof(float)>>>(bias, out);
}

// round 10
// speedup vs baseline: 1.0208x; 1.0208x over previous
#include <cuda_runtime.h>
#include <math.h>

// ---------------- problem constants ----------------
#define NN    50000
#define FIN   256
#define FOUT  128
#define HH    128
#define DD    16
#define EE    (NN*DD)     // 800000
#define G4    512         // 4*H

// ---------------- scratch ----------------
__device__ float    g_P2[(size_t)NN*G4];       // 102.4MB  P2 = X @ Wcomb^T (permuted cols)
__device__ float    g_ssrc[NN];
__device__ float    g_strg[NN];
__device__ float    g_scores[EE];
__device__ unsigned g_gmax;
__device__ int      g_seqsrc[EE];
__device__ float    g_seqatt[EE];
__device__ float    g_wih_p[G4*HH];            // permuted w_ih  [512 rows][128]
__device__ float    g_whh_pT[HH*G4];           // permuted w_hh  [128 k][512 cols] K-major
__device__ float    g_bcat[G4];
__device__ float    g_wcomb[G4*FIN];           // [512][256] = wih_p @ Wp
__device__ float    g_va[FIN];
__device__ float    g_vt[FIN];

// ---------------- helpers ----------------
__device__ __forceinline__ unsigned fenc(float f) {
    unsigned i = __float_as_uint(f);
    return (i & 0x80000000u) ? ~i : (i | 0x80000000u);
}
__device__ __forceinline__ float fdec(unsigned u) {
    return (u & 0x80000000u) ? __uint_as_float(u ^ 0x80000000u) : __uint_as_float(~u);
}
__device__ __forceinline__ float tanh_fast(float x) {
    float r;
    asm("tanh.approx.f32 %0, %1;" : "=f"(r) : "f"(x));
    return r;
}
__device__ __forceinline__ float sig_fast(float x) {
    return fmaf(tanh_fast(0.5f * x), 0.5f, 0.5f);
}
// packed f32x2 ops
typedef unsigned long long ull;
__device__ __forceinline__ ull pack2(float x, float y) {
    ull r; asm("mov.b64 %0, {%1,%2};" : "=l"(r) : "f"(x), "f"(y)); return r;
}
__device__ __forceinline__ float2 unpack2(ull v) {
    float2 r; asm("mov.b64 {%0,%1}, %2;" : "=f"(r.x), "=f"(r.y) : "l"(v)); return r;
}
__device__ __forceinline__ ull ffma2_(ull a, ull b, ull c) {
    ull d; asm("fma.rn.f32x2 %0, %1, %2, %3;" : "=l"(d) : "l"(a), "l"(b), "l"(c)); return d;
}
__device__ __forceinline__ ull add2_(ull a, ull b) {
    ull d; asm("add.rn.f32x2 %0, %1, %2;" : "=l"(d) : "l"(a), "l"(b)); return d;
}
// cp.async helpers
__device__ __forceinline__ void cp16(unsigned dst, const void* src) {
    asm volatile("cp.async.ca.shared.global [%0], [%1], 16;" :: "r"(dst), "l"(src));
}
__device__ __forceinline__ void cp_commit() { asm volatile("cp.async.commit_group;"); }
template <int N>
__device__ __forceinline__ void cp_wait() { asm volatile("cp.async.wait_group %0;" :: "n"(N)); }

// ---------------- kernel: build permuted weights ----------------
__global__ void prep_w_k(const float* __restrict__ wih, const float* __restrict__ whh,
                         const float* __restrict__ bih, const float* __restrict__ bhh) {
    int idx = blockIdx.x * blockDim.x + threadIdx.x;   // 0..65535
    int R = idx >> 7;
    int k = idx & 127;
    int ch = R >> 7, c = R & 127;
    int gate = c >> 5, dd = c & 31;
    int grow = gate * 128 + ch * 32 + dd;
    g_wih_p[R * 128 + k]  = wih[grow * 128 + k];
    g_whh_pT[k * 512 + R] = whh[grow * 128 + k];
    if (k == 0) g_bcat[R] = bih[grow] + bhh[grow];
}

// ---------------- kernel: Wcomb = wih_p @ Wp  (512 x 256) ----------------
__global__ void wcomb_k(const float* __restrict__ Wp) {
    __shared__ float wr[128];
    int R = blockIdx.x;
    int tid = threadIdx.x;   // 256
    if (tid < 128) wr[tid] = g_wih_p[R * 128 + tid];
    __syncthreads();
    float acc = 0.0f;
#pragma unroll 8
    for (int j = 0; j < 128; j++)
        acc = fmaf(wr[j], Wp[j * 256 + tid], acc);
    g_wcomb[R * 256 + tid] = acc;
}

// ---------------- kernel: va = Wp^T a_src, vt = Wp^T a_trg ----------------
__global__ void vav_k(const float* __restrict__ Wp,
                      const float* __restrict__ as, const float* __restrict__ at) {
    int tid = threadIdx.x;   // 256
    float s1 = 0.0f, s2 = 0.0f;
#pragma unroll 8
    for (int j = 0; j < 128; j++) {
        float w = Wp[j * 256 + tid];
        s1 = fmaf(as[j], w, s1);
        s2 = fmaf(at[j], w, s2);
    }
    g_va[tid] = s1;
    g_vt[tid] = s2;
}

// ---------------- kernel: per-node attention dots on X (256-dim) ----------------
__global__ void sdotsX_k(const float* __restrict__ x) {
    int gtid = blockIdx.x * blockDim.x + threadIdx.x;
    int warp = gtid >> 5;
    int lane = gtid & 31;
    if (warp >= NN) return;
    const float4* xr = (const float4*)(x + (size_t)warp * 256);
    float4 x1 = xr[lane];
    float4 x2 = xr[32 + lane];
    float4 a1 = ((const float4*)g_va)[lane];
    float4 a2 = ((const float4*)g_va)[32 + lane];
    float4 b1 = ((const float4*)g_vt)[lane];
    float4 b2 = ((const float4*)g_vt)[32 + lane];
    float s1 = x1.x*a1.x + x1.y*a1.y + x1.z*a1.z + x1.w*a1.w
             + x2.x*a2.x + x2.y*a2.y + x2.z*a2.z + x2.w*a2.w;
    float s2 = x1.x*b1.x + x1.y*b1.y + x1.z*b1.z + x1.w*b1.w
             + x2.x*b2.x + x2.y*b2.y + x2.z*b2.z + x2.w*b2.w;
#pragma unroll
    for (int o = 16; o; o >>= 1) {
        s1 += __shfl_xor_sync(0xffffffffu, s1, o);
        s2 += __shfl_xor_sync(0xffffffffu, s2, o);
    }
    if (lane == 0) { g_ssrc[warp] = s1; g_strg[warp] = s2; }
}

// ---------------- kernel: P2 = X @ Wcomb^T (FFMA2, row-paired, K=256) ----------
__global__ __launch_bounds__(256) void p2x_k(const float* __restrict__ x) {
    __shared__ float xs2[32 * 66];
    __shared__ float ws[256 * 33];
    int tid = threadIdx.x, lane = tid & 31, wrp = tid >> 5;
    int n0 = blockIdx.x * 64;
    int coff = blockIdx.y * 256;
    ull accp[4][8];
#pragma unroll
    for (int rp = 0; rp < 4; rp++)
#pragma unroll
        for (int j = 0; j < 8; j++) accp[rp][j] = 0ull;

    for (int k0 = 0; k0 < 256; k0 += 32) {
        __syncthreads();
#pragma unroll
        for (int v = 0; v < 8; v++) {
            int idx = tid + v * 256;
            int r = idx >> 5, kk = idx & 31;
            int n = n0 + r;
            xs2[kk * 66 + r] = (n < NN) ? x[(size_t)n * 256 + k0 + kk] : 0.0f;
        }
#pragma unroll
        for (int v = 0; v < 32; v++) {
            int idx = tid + v * 256;
            int c = idx >> 5, kk = idx & 31;
            ws[c * 33 + kk] = g_wcomb[(coff + c) * 256 + k0 + kk];
        }
        __syncthreads();
#pragma unroll 4
        for (int kk = 0; kk < 32; kk++) {
            ull uvp[4], wvp[8];
#pragma unroll
            for (int rp = 0; rp < 4; rp++) {
                float2 u2 = *(const float2*)(xs2 + kk * 66 + wrp * 8 + 2 * rp);
                uvp[rp] = pack2(u2.x, u2.y);
            }
#pragma unroll
            for (int j = 0; j < 8; j++) {
                float wv = ws[(j * 32 + lane) * 33 + kk];
                wvp[j] = pack2(wv, wv);
            }
#pragma unroll
            for (int rp = 0; rp < 4; rp++)
#pragma unroll
                for (int j = 0; j < 8; j++)
                    accp[rp][j] = ffma2_(uvp[rp], wvp[j], accp[rp][j]);
        }
    }
#pragma unroll
    for (int rp = 0; rp < 4; rp++) {
        int n = n0 + wrp * 8 + 2 * rp;
#pragma unroll
        for (int j = 0; j < 8; j++) {
            float2 res = unpack2(accp[rp][j]);
            int c = coff + j * 32 + lane;
            if (n < NN)     g_P2[(size_t)n * 512 + c] = res.x;
            if (n + 1 < NN) g_P2[(size_t)(n + 1) * 512 + c] = res.y;
        }
    }
}

// ---------------- kernel: skip GEMM  out = X @ Wsk^T  (128 cols) ----------------
__global__ __launch_bounds__(256) void skip_k(const float* __restrict__ x,
                                              const float* __restrict__ Wsk,
                                              float* __restrict__ out) {
    __shared__ float xs2[32 * 66];
    __shared__ float ws[128 * 33];
    int tid = threadIdx.x, lane = tid & 31, wrp = tid >> 5;
    int n0 = blockIdx.x * 64;
    ull accp[4][4];
#pragma unroll
    for (int rp = 0; rp < 4; rp++)
#pragma unroll
        for (int j = 0; j < 4; j++) accp[rp][j] = 0ull;

    for (int k0 = 0; k0 < 256; k0 += 32) {
        __syncthreads();
#pragma unroll
        for (int v = 0; v < 8; v++) {
            int idx = tid + v * 256;
            int r = idx >> 5, kk = idx & 31;
            int n = n0 + r;
            xs2[kk * 66 + r] = (n < NN) ? x[(size_t)n * 256 + k0 + kk] : 0.0f;
        }
#pragma unroll
        for (int v = 0; v < 16; v++) {
            int idx = tid + v * 256;
            int c = idx >> 5, kk = idx & 31;
            ws[c * 33 + kk] = Wsk[c * 256 + k0 + kk];
        }
        __syncthreads();
#pragma unroll 4
        for (int kk = 0; kk < 32; kk++) {
            ull uvp[4], wvp[4];
#pragma unroll
            for (int rp = 0; rp < 4; rp++) {
                float2 u2 = *(const float2*)(xs2 + kk * 66 + wrp * 8 + 2 * rp);
                uvp[rp] = pack2(u2.x, u2.y);
            }
#pragma unroll
            for (int j = 0; j < 4; j++) {
                float wv = ws[(j * 32 + lane) * 33 + kk];
                wvp[j] = pack2(wv, wv);
            }
#pragma unroll
            for (int rp = 0; rp < 4; rp++)
#pragma unroll
                for (int j = 0; j < 4; j++)
                    accp[rp][j] = ffma2_(uvp[rp], wvp[j], accp[rp][j]);
        }
    }
#pragma unroll
    for (int rp = 0; rp < 4; rp++) {
        int n = n0 + wrp * 8 + 2 * rp;
#pragma unroll
        for (int j = 0; j < 4; j++) {
            float2 res = unpack2(accp[rp][j]);
            int c = j * 32 + lane;
            if (n < NN)     out[(size_t)n * 128 + c] = res.x;
            if (n + 1 < NN) out[(size_t)(n + 1) * 128 + c] = res.y;
        }
    }
}

__global__ void initmax_k() { g_gmax = 0u; }

// ---------------- kernel: edge scores + global max ----------------
__global__ void scores_k(const int* __restrict__ ei) {
    int e = blockIdx.x * blockDim.x + threadIdx.x;
    int s = ei[e];
    int t = ei[EE + e];
    float sc = g_ssrc[s] + g_strg[t];
    sc = (sc >= 0.0f) ? sc : 0.2f * sc;
    g_scores[e] = sc;
    float m = sc;
#pragma unroll
    for (int o = 16; o; o >>= 1) m = fmaxf(m, __shfl_xor_sync(0xffffffffu, m, o));
    __shared__ float wm[8];
    int lane = threadIdx.x & 31, wid = threadIdx.x >> 5;
    if (lane == 0) wm[wid] = m;
    __syncthreads();
    if (threadIdx.x == 0) {
        float mm = wm[0];
#pragma unroll
        for (int w = 1; w < 8; w++) mm = fmaxf(mm, wm[w]);
        atomicMax(&g_gmax, fenc(mm));
    }
}

// ---------------- kernel: softmax + stable sort ----------------
__global__ void sort_k(const int* __restrict__ ei) {
    int n = blockIdx.x * blockDim.x + threadIdx.x;
    if (n >= NN) return;
    float gmax = fdec(g_gmax);
    float ev[DD], srt[DD];
    int idx[DD];
    float denom = 0.0f;
#pragma unroll
    for (int j = 0; j < DD; j++) {
        float e = expf(g_scores[n * DD + j] - gmax);
        ev[j] = e;
        denom += e;
    }
    denom += 1e-16f;
    for (int j = 0; j < DD; j++) {
        float key = ev[j];
        int pos = j;
        while (pos > 0 && srt[pos - 1] <= key) {
            srt[pos] = srt[pos - 1];
            idx[pos] = idx[pos - 1];
            pos--;
        }
        srt[pos] = key;
        idx[pos] = j;
    }
    float inv = 1.0f / denom;
#pragma unroll
    for (int t = 0; t < DD; t++) {
        int j = idx[t];
        g_seqsrc[n * DD + t] = ei[n * DD + j];
        g_seqatt[n * DD + t] = srt[t] * inv;
    }
}

// ---------------- kernel: backward LSTM, FFMA2, duplicated-h + R7 schedule ------
// 64 nodes / block, 256 threads. Warp owns 8 rows; lane (hl=lane>>4, p=lane&15)
// owns hidden-dim pairs {2p,2p+1} of chunks (hl) and (hl+2).
// h stored DUPLICATED ([row][k][2]); per 2-kk the row operand is ONE LDS.128
// per row (reused across both kk), w pairs load directly as 64-bit. c in regs.
#define U2_STR 264
#define KT 32
#define W_STR 520
#define LSTM_SM_FLOATS (64*U2_STR + 2*KT*W_STR + 160)

__global__ __launch_bounds__(256, 1) void lstm_k(const float* __restrict__ bias,
                                                 float* __restrict__ out) {
    extern __shared__ float sm[];
    float* u    = sm;                          // [64][U2_STR] duplicated h (in-place)
    float* wsm  = sm + 64 * U2_STR;            // [2][KT][W_STR] w tiles
    float* satt = wsm + 2 * KT * W_STR;        // [64]
    int*   ssrc = (int*)(satt + 64);           // [64]

    int tid = threadIdx.x, lane = tid & 31, wrp = tid >> 5;
    int hl = lane >> 4, p = lane & 15;
    int n0 = blockIdx.x * 64;
    unsigned wsm_s = (unsigned)__cvta_generic_to_shared(wsm);

    int co[8];
#pragma unroll
    for (int jj = 0; jj < 8; jj++)
        co[jj] = (hl + 2 * (jj >> 2)) * 128 + (jj & 3) * 32 + 2 * p;

    ull bcp[8];
#pragma unroll
    for (int jj = 0; jj < 8; jj++) {
        float2 b2 = *(const float2*)(g_bcat + co[jj]);
        bcp[jj] = pack2(b2.x, b2.y);
    }

    float2 creg2[8][2];
#pragma unroll
    for (int i = 0; i < 8; i++)
#pragma unroll
        for (int cs = 0; cs < 2; cs++) creg2[i][cs] = make_float2(0.0f, 0.0f);

    for (int idx = tid; idx < 64 * U2_STR; idx += 256) u[idx] = 0.0f;
    __syncthreads();

#pragma unroll 1
    for (int t = 0; t < DD; t++) {
        if (tid < 64) {
            int n = n0 + tid;
            if (n < NN) {
                ssrc[tid] = g_seqsrc[n * DD + t];
                satt[tid] = g_seqatt[n * DD + t];
            } else {
                ssrc[tid] = 0;
                satt[tid] = 0.0f;
            }
        }
        __syncthreads();

        ull accp[8][8];
#pragma unroll
        for (int i = 0; i < 8; i++)
#pragma unroll
            for (int jj = 0; jj < 8; jj++) accp[i][jj] = 0ull;

        if (t > 0) {
#pragma unroll
            for (int v = 0; v < 16; v++) {
                int f4 = tid + v * 256;
                int kk = f4 >> 7, c4 = f4 & 127;
                cp16(wsm_s + (kk * W_STR + c4 * 4) * 4,
                     g_whh_pT + (size_t)kk * 512 + c4 * 4);
            }
            cp_commit();

#pragma unroll 1
            for (int kt = 0; kt < 4; kt++) {
                if (kt < 3) {
                    unsigned db = wsm_s + (((kt + 1) & 1) * KT * W_STR) * 4;
#pragma unroll
                    for (int v = 0; v < 16; v++) {
                        int f4 = tid + v * 256;
                        int kk = f4 >> 7, c4 = f4 & 127;
                        cp16(db + (kk * W_STR + c4 * 4) * 4,
                             g_whh_pT + (size_t)((kt + 1) * KT + kk) * 512 + c4 * 4);
                    }
                    cp_commit();
                    cp_wait<1>();
                } else {
                    cp_wait<0>();
                }
                __syncthreads();

                const float* wb  = wsm + (kt & 1) * KT * W_STR;
                const float* ubd = u + kt * KT * 2;   // duplicated: k -> 2k floats
#pragma unroll 4
                for (int kk2 = 0; kk2 < KT / 2; kk2++) {
                    ulonglong2 ud[8];
#pragma unroll
                    for (int i = 0; i < 8; i++)
                        ud[i] = *(const ulonglong2*)(ubd + (wrp * 8 + i) * U2_STR + 4 * kk2);
#pragma unroll
                    for (int sub = 0; sub < 2; sub++) {
                        ull wvp[8];
#pragma unroll
                        for (int jj = 0; jj < 8; jj++)
                            wvp[jj] = *(const ull*)(wb + (2 * kk2 + sub) * W_STR + co[jj]);
#pragma unroll
                        for (int i = 0; i < 8; i++) {
                            ull up = sub ? ud[i].y : ud[i].x;
#pragma unroll
                            for (int jj = 0; jj < 8; jj++)
                                accp[i][jj] = ffma2_(up, wvp[jj], accp[i][jj]);
                        }
                    }
                }
                __syncthreads();
            }
        }

        // x-contribution: acc = acc + bias + att * P2[src]  (batched 2 rows)
#pragma unroll
        for (int b = 0; b < 4; b++) {
            ull pvp[2][8];
#pragma unroll
            for (int i2 = 0; i2 < 2; i2++) {
                int s = ssrc[wrp * 8 + b * 2 + i2];
                const float* pp = g_P2 + (size_t)s * 512;
#pragma unroll
                for (int jj = 0; jj < 8; jj++)
                    pvp[i2][jj] = *(const ull*)(pp + co[jj]);
            }
#pragma unroll
            for (int i2 = 0; i2 < 2; i2++) {
                int i = b * 2 + i2;
                float a = satt[wrp * 8 + i];
                ull ap = pack2(a, a);
#pragma unroll
                for (int jj = 0; jj < 8; jj++)
                    accp[i][jj] = ffma2_(ap, pvp[i2][jj], add2_(accp[i][jj], bcp[jj]));
            }
        }

        // gate activations + c/h update (duplicated h, one STS.128 per dim-pair)
#pragma unroll
        for (int i = 0; i < 8; i++) {
#pragma unroll
            for (int cs = 0; cs < 2; cs++) {
                float2 iv = unpack2(accp[i][cs * 4 + 0]);
                float2 fv = unpack2(accp[i][cs * 4 + 1]);
                float2 gv = unpack2(accp[i][cs * 4 + 2]);
                float2 ov = unpack2(accp[i][cs * 4 + 3]);
                float2 cp2 = creg2[i][cs];
                float c0 = fmaf(sig_fast(fv.x), cp2.x, sig_fast(iv.x) * tanh_fast(gv.x));
                float c1 = fmaf(sig_fast(fv.y), cp2.y, sig_fast(iv.y) * tanh_fast(gv.y));
                creg2[i][cs] = make_float2(c0, c1);
                float h0 = sig_fast(ov.x) * tanh_fast(c0);
                float h1 = sig_fast(ov.y) * tanh_fast(c1);
                int dbase = ((hl + 2 * cs) * 32 + 2 * p) * 2;
                *(float4*)(u + (wrp * 8 + i) * U2_STR + dbase) =
                    make_float4(h0, h0, h1, h1);
            }
        }
        __syncthreads();
    }

    // epilogue: final h in u (duplicated layout)
    for (int idx = tid; idx < 64 * 128; idx += 256) {
        int r = idx >> 7, d = idx & 127;
        int n = n0 + r;
        if (n < NN) {
            float v = u[r * U2_STR + 2 * d] + out[(size_t)n * 128 + d] + bias[d];
            out[(size_t)n * 128 + d] = (v >= 0.0f) ? v : 0.01f * v;
        }
    }
}

// ---------------- launch ----------------
extern "C" void kernel_launch(void* const* d_in, const int* in_sizes, int n_in,
                              void* d_out, int out_size) {
    const float* x    = (const float*)d_in[0];
    const float* Wp   = (const float*)d_in[1];
    const float* asrc = (const float*)d_in[2];
    const float* atrg = (const float*)d_in[3];
    const float* Wsk  = (const float*)d_in[4];
    const float* bias = (const float*)d_in[5];
    // d_in[6..9]: forward-direction weights, unused by the reference
    const float* wihb = (const float*)d_in[10];
    const float* whhb = (const float*)d_in[11];
    const float* bihb = (const float*)d_in[12];
    const float* bhhb = (const float*)d_in[13];
    const int*   ei   = (const int*)d_in[14];
    float* out = (float*)d_out;

    (void)in_sizes; (void)n_in; (void)out_size;

    cudaFuncSetAttribute(lstm_k, cudaFuncAttributeMaxDynamicSharedMemorySize,
                         LSTM_SM_FLOATS * (int)sizeof(float));

    prep_w_k<<<256, 256>>>(wihb, whhb, bihb, bhhb);
    wcomb_k<<<512, 256>>>(Wp);
    vav_k<<<1, 256>>>(Wp, asrc, atrg);
    sdotsX_k<<<(NN * 32 + 255) / 256, 256>>>(x);
    {
        dim3 g((NN + 63) / 64, 2);
        p2x_k<<<g, 256>>>(x);
    }
    skip_k<<<(NN + 63) / 64, 256>>>(x, Wsk, out);
    initmax_k<<<1, 1>>>();
    scores_k<<<EE / 256, 256>>>(ei);
    sort_k<<<(NN + 255) / 256, 256>>>(ei);
    lstm_k<<<(NN + 63) / 64, 256, LSTM_SM_FLOATS * (int)sizeof(float)>>>(bias, out);
}

// round 11
// speedup vs baseline: 1.0908x; 1.0685x over previous
#include <cuda_runtime.h>
#include <math.h>

// ---------------- problem constants ----------------
#define NN    50000
#define FIN   256
#define FOUT  128
#define HH    128
#define DD    16
#define EE    (NN*DD)     // 800000
#define G4    512         // 4*H

// ---------------- scratch ----------------
__device__ float    g_P2[(size_t)NN*G4];       // 102.4MB  P2 = X @ Wcomb^T (permuted cols)
__device__ float    g_ssrc[NN];
__device__ float    g_strg[NN];
__device__ float    g_scores[EE];
__device__ unsigned g_gmax;
__device__ int      g_seqsrc[EE];
__device__ float    g_seqatt[EE];
__device__ float    g_wih_p[G4*HH];            // permuted w_ih  [512 rows][128]
__device__ float    g_whh_pT[HH*G4];           // permuted w_hh  [128 k][512 cols] K-major
__device__ float    g_bcat[G4];
__device__ float    g_wcomb[G4*FIN];           // [512][256] = wih_p @ Wp
__device__ float    g_va[FIN];
__device__ float    g_vt[FIN];

// ---------------- helpers ----------------
__device__ __forceinline__ unsigned fenc(float f) {
    unsigned i = __float_as_uint(f);
    return (i & 0x80000000u) ? ~i : (i | 0x80000000u);
}
__device__ __forceinline__ float fdec(unsigned u) {
    return (u & 0x80000000u) ? __uint_as_float(u ^ 0x80000000u) : __uint_as_float(~u);
}
__device__ __forceinline__ float tanh_fast(float x) {
    float r;
    asm("tanh.approx.f32 %0, %1;" : "=f"(r) : "f"(x));
    return r;
}
__device__ __forceinline__ float sig_fast(float x) {
    return fmaf(tanh_fast(0.5f * x), 0.5f, 0.5f);
}
// packed f32x2 ops
typedef unsigned long long ull;
__device__ __forceinline__ ull pack2(float x, float y) {
    ull r; asm("mov.b64 %0, {%1,%2};" : "=l"(r) : "f"(x), "f"(y)); return r;
}
__device__ __forceinline__ float2 unpack2(ull v) {
    float2 r; asm("mov.b64 {%0,%1}, %2;" : "=f"(r.x), "=f"(r.y) : "l"(v)); return r;
}
__device__ __forceinline__ ull ffma2_(ull a, ull b, ull c) {
    ull d; asm("fma.rn.f32x2 %0, %1, %2, %3;" : "=l"(d) : "l"(a), "l"(b), "l"(c)); return d;
}
__device__ __forceinline__ ull add2_(ull a, ull b) {
    ull d; asm("add.rn.f32x2 %0, %1, %2;" : "=l"(d) : "l"(a), "l"(b)); return d;
}
// cp.async helpers
__device__ __forceinline__ void cp16(unsigned dst, const void* src) {
    asm volatile("cp.async.ca.shared.global [%0], [%1], 16;" :: "r"(dst), "l"(src));
}
__device__ __forceinline__ void cp_commit() { asm volatile("cp.async.commit_group;"); }
template <int N>
__device__ __forceinline__ void cp_wait() { asm volatile("cp.async.wait_group %0;" :: "n"(N)); }

// ---------------- kernel: build permuted weights ----------------
__global__ void prep_w_k(const float* __restrict__ wih, const float* __restrict__ whh,
                         const float* __restrict__ bih, const float* __restrict__ bhh) {
    int idx = blockIdx.x * blockDim.x + threadIdx.x;   // 0..65535
    int R = idx >> 7;
    int k = idx & 127;
    int ch = R >> 7, c = R & 127;
    int gate = c >> 5, dd = c & 31;
    int grow = gate * 128 + ch * 32 + dd;
    g_wih_p[R * 128 + k]  = wih[grow * 128 + k];
    g_whh_pT[k * 512 + R] = whh[grow * 128 + k];
    if (k == 0) g_bcat[R] = bih[grow] + bhh[grow];
}

// ---------------- kernel: Wcomb = wih_p @ Wp  (512 x 256) ----------------
__global__ void wcomb_k(const float* __restrict__ Wp) {
    __shared__ float wr[128];
    int R = blockIdx.x;
    int tid = threadIdx.x;   // 256
    if (tid < 128) wr[tid] = g_wih_p[R * 128 + tid];
    __syncthreads();
    float acc = 0.0f;
#pragma unroll 8
    for (int j = 0; j < 128; j++)
        acc = fmaf(wr[j], Wp[j * 256 + tid], acc);
    g_wcomb[R * 256 + tid] = acc;
}

// ---------------- kernel: va = Wp^T a_src, vt = Wp^T a_trg ----------------
__global__ void vav_k(const float* __restrict__ Wp,
                      const float* __restrict__ as, const float* __restrict__ at) {
    int tid = threadIdx.x;   // 256
    float s1 = 0.0f, s2 = 0.0f;
#pragma unroll 8
    for (int j = 0; j < 128; j++) {
        float w = Wp[j * 256 + tid];
        s1 = fmaf(as[j], w, s1);
        s2 = fmaf(at[j], w, s2);
    }
    g_va[tid] = s1;
    g_vt[tid] = s2;
}

// ---------------- kernel: per-node attention dots on X (256-dim) ----------------
__global__ void sdotsX_k(const float* __restrict__ x) {
    int gtid = blockIdx.x * blockDim.x + threadIdx.x;
    int warp = gtid >> 5;
    int lane = gtid & 31;
    if (warp >= NN) return;
    const float4* xr = (const float4*)(x + (size_t)warp * 256);
    float4 x1 = xr[lane];
    float4 x2 = xr[32 + lane];
    float4 a1 = ((const float4*)g_va)[lane];
    float4 a2 = ((const float4*)g_va)[32 + lane];
    float4 b1 = ((const float4*)g_vt)[lane];
    float4 b2 = ((const float4*)g_vt)[32 + lane];
    float s1 = x1.x*a1.x + x1.y*a1.y + x1.z*a1.z + x1.w*a1.w
             + x2.x*a2.x + x2.y*a2.y + x2.z*a2.z + x2.w*a2.w;
    float s2 = x1.x*b1.x + x1.y*b1.y + x1.z*b1.z + x1.w*b1.w
             + x2.x*b2.x + x2.y*b2.y + x2.z*b2.z + x2.w*b2.w;
#pragma unroll
    for (int o = 16; o; o >>= 1) {
        s1 += __shfl_xor_sync(0xffffffffu, s1, o);
        s2 += __shfl_xor_sync(0xffffffffu, s2, o);
    }
    if (lane == 0) { g_ssrc[warp] = s1; g_strg[warp] = s2; }
}

// ---------------- kernel: P2 = X @ Wcomb^T (FFMA2, row-paired, K=256) ----------
__global__ __launch_bounds__(256) void p2x_k(const float* __restrict__ x) {
    __shared__ float xs2[32 * 66];
    __shared__ float ws[256 * 33];
    int tid = threadIdx.x, lane = tid & 31, wrp = tid >> 5;
    int n0 = blockIdx.x * 64;
    int coff = blockIdx.y * 256;
    ull accp[4][8];
#pragma unroll
    for (int rp = 0; rp < 4; rp++)
#pragma unroll
        for (int j = 0; j < 8; j++) accp[rp][j] = 0ull;

    for (int k0 = 0; k0 < 256; k0 += 32) {
        __syncthreads();
#pragma unroll
        for (int v = 0; v < 8; v++) {
            int idx = tid + v * 256;
            int r = idx >> 5, kk = idx & 31;
            int n = n0 + r;
            xs2[kk * 66 + r] = (n < NN) ? x[(size_t)n * 256 + k0 + kk] : 0.0f;
        }
#pragma unroll
        for (int v = 0; v < 32; v++) {
            int idx = tid + v * 256;
            int c = idx >> 5, kk = idx & 31;
            ws[c * 33 + kk] = g_wcomb[(coff + c) * 256 + k0 + kk];
        }
        __syncthreads();
#pragma unroll 4
        for (int kk = 0; kk < 32; kk++) {
            ull uvp[4], wvp[8];
#pragma unroll
            for (int rp = 0; rp < 4; rp++) {
                float2 u2 = *(const float2*)(xs2 + kk * 66 + wrp * 8 + 2 * rp);
                uvp[rp] = pack2(u2.x, u2.y);
            }
#pragma unroll
            for (int j = 0; j < 8; j++) {
                float wv = ws[(j * 32 + lane) * 33 + kk];
                wvp[j] = pack2(wv, wv);
            }
#pragma unroll
            for (int rp = 0; rp < 4; rp++)
#pragma unroll
                for (int j = 0; j < 8; j++)
                    accp[rp][j] = ffma2_(uvp[rp], wvp[j], accp[rp][j]);
        }
    }
#pragma unroll
    for (int rp = 0; rp < 4; rp++) {
        int n = n0 + wrp * 8 + 2 * rp;
#pragma unroll
        for (int j = 0; j < 8; j++) {
            float2 res = unpack2(accp[rp][j]);
            int c = coff + j * 32 + lane;
            if (n < NN)     g_P2[(size_t)n * 512 + c] = res.x;
            if (n + 1 < NN) g_P2[(size_t)(n + 1) * 512 + c] = res.y;
        }
    }
}

// ---------------- kernel: skip GEMM  out = X @ Wsk^T  (128 cols) ----------------
__global__ __launch_bounds__(256) void skip_k(const float* __restrict__ x,
                                              const float* __restrict__ Wsk,
                                              float* __restrict__ out) {
    __shared__ float xs2[32 * 66];
    __shared__ float ws[128 * 33];
    int tid = threadIdx.x, lane = tid & 31, wrp = tid >> 5;
    int n0 = blockIdx.x * 64;
    ull accp[4][4];
#pragma unroll
    for (int rp = 0; rp < 4; rp++)
#pragma unroll
        for (int j = 0; j < 4; j++) accp[rp][j] = 0ull;

    for (int k0 = 0; k0 < 256; k0 += 32) {
        __syncthreads();
#pragma unroll
        for (int v = 0; v < 8; v++) {
            int idx = tid + v * 256;
            int r = idx >> 5, kk = idx & 31;
            int n = n0 + r;
            xs2[kk * 66 + r] = (n < NN) ? x[(size_t)n * 256 + k0 + kk] : 0.0f;
        }
#pragma unroll
        for (int v = 0; v < 16; v++) {
            int idx = tid + v * 256;
            int c = idx >> 5, kk = idx & 31;
            ws[c * 33 + kk] = Wsk[c * 256 + k0 + kk];
        }
        __syncthreads();
#pragma unroll 4
        for (int kk = 0; kk < 32; kk++) {
            ull uvp[4], wvp[4];
#pragma unroll
            for (int rp = 0; rp < 4; rp++) {
                float2 u2 = *(const float2*)(xs2 + kk * 66 + wrp * 8 + 2 * rp);
                uvp[rp] = pack2(u2.x, u2.y);
            }
#pragma unroll
            for (int j = 0; j < 4; j++) {
                float wv = ws[(j * 32 + lane) * 33 + kk];
                wvp[j] = pack2(wv, wv);
            }
#pragma unroll
            for (int rp = 0; rp < 4; rp++)
#pragma unroll
                for (int j = 0; j < 4; j++)
                    accp[rp][j] = ffma2_(uvp[rp], wvp[j], accp[rp][j]);
        }
    }
#pragma unroll
    for (int rp = 0; rp < 4; rp++) {
        int n = n0 + wrp * 8 + 2 * rp;
#pragma unroll
        for (int j = 0; j < 4; j++) {
            float2 res = unpack2(accp[rp][j]);
            int c = j * 32 + lane;
            if (n < NN)     out[(size_t)n * 128 + c] = res.x;
            if (n + 1 < NN) out[(size_t)(n + 1) * 128 + c] = res.y;
        }
    }
}

__global__ void initmax_k() { g_gmax = 0u; }

// ---------------- kernel: edge scores + global max ----------------
__global__ void scores_k(const int* __restrict__ ei) {
    int e = blockIdx.x * blockDim.x + threadIdx.x;
    int s = ei[e];
    int t = ei[EE + e];
    float sc = g_ssrc[s] + g_strg[t];
    sc = (sc >= 0.0f) ? sc : 0.2f * sc;
    g_scores[e] = sc;
    float m = sc;
#pragma unroll
    for (int o = 16; o; o >>= 1) m = fmaxf(m, __shfl_xor_sync(0xffffffffu, m, o));
    __shared__ float wm[8];
    int lane = threadIdx.x & 31, wid = threadIdx.x >> 5;
    if (lane == 0) wm[wid] = m;
    __syncthreads();
    if (threadIdx.x == 0) {
        float mm = wm[0];
#pragma unroll
        for (int w = 1; w < 8; w++) mm = fmaxf(mm, wm[w]);
        atomicMax(&g_gmax, fenc(mm));
    }
}

// ---------------- kernel: softmax + stable sort ----------------
__global__ void sort_k(const int* __restrict__ ei) {
    int n = blockIdx.x * blockDim.x + threadIdx.x;
    if (n >= NN) return;
    float gmax = fdec(g_gmax);
    float ev[DD], srt[DD];
    int idx[DD];
    float denom = 0.0f;
#pragma unroll
    for (int j = 0; j < DD; j++) {
        float e = expf(g_scores[n * DD + j] - gmax);
        ev[j] = e;
        denom += e;
    }
    denom += 1e-16f;
    for (int j = 0; j < DD; j++) {
        float key = ev[j];
        int pos = j;
        while (pos > 0 && srt[pos - 1] <= key) {
            srt[pos] = srt[pos - 1];
            idx[pos] = idx[pos - 1];
            pos--;
        }
        srt[pos] = key;
        idx[pos] = j;
    }
    float inv = 1.0f / denom;
#pragma unroll
    for (int t = 0; t < DD; t++) {
        int j = idx[t];
        g_seqsrc[n * DD + t] = ei[n * DD + j];
        g_seqatt[n * DD + t] = srt[t] * inv;
    }
}

// ---------------- kernel: backward LSTM (R7 schedule — proven fastest) ----------
// 64 nodes / block, 256 threads (8 warps). Warp owns 8 rows; lane (hl=lane>>4,
// p=lane&15) owns hidden-dim pairs {2p,2p+1} of chunks (hl) and (hl+2).
// One GEMM pass per timestep over all 512 gate cols; h in place; c in registers.
#define U_STR 132
#define KT 32
#define W_STR 520
#define LSTM_SM_FLOATS (64*U_STR + 2*KT*W_STR + 160)

__global__ __launch_bounds__(256, 1) void lstm_k(const float* __restrict__ bias,
                                                 float* __restrict__ out) {
    extern __shared__ float sm[];
    float* u    = sm;                          // [64][U_STR] h (in-place)
    float* wsm  = sm + 64 * U_STR;             // [2][KT][W_STR] w tiles
    float* satt = wsm + 2 * KT * W_STR;        // [64]
    int*   ssrc = (int*)(satt + 64);           // [64]

    int tid = threadIdx.x, lane = tid & 31, wrp = tid >> 5;
    int hl = lane >> 4, p = lane & 15;
    int n0 = blockIdx.x * 64;
    unsigned wsm_s = (unsigned)__cvta_generic_to_shared(wsm);

    // col offsets: jj = cs*4 + g -> col = (hl+2cs)*128 + g*32 + 2p
    int co[8];
#pragma unroll
    for (int jj = 0; jj < 8; jj++)
        co[jj] = (hl + 2 * (jj >> 2)) * 128 + (jj & 3) * 32 + 2 * p;

    // bias pairs
    ull bcp[8];
#pragma unroll
    for (int jj = 0; jj < 8; jj++) {
        float2 b2 = *(const float2*)(g_bcat + co[jj]);
        bcp[jj] = pack2(b2.x, b2.y);
    }

    // cell state: creg2[row][cs] = c for dims (hl+2cs)*32 + {2p,2p+1}
    float2 creg2[8][2];
#pragma unroll
    for (int i = 0; i < 8; i++)
#pragma unroll
        for (int cs = 0; cs < 2; cs++) creg2[i][cs] = make_float2(0.0f, 0.0f);

#pragma unroll 1
    for (int t = 0; t < DD; t++) {
        if (tid < 64) {
            int n = n0 + tid;
            if (n < NN) {
                ssrc[tid] = g_seqsrc[n * DD + t];
                satt[tid] = g_seqatt[n * DD + t];
            } else {
                ssrc[tid] = 0;
                satt[tid] = 0.0f;
            }
        }
        __syncthreads();

        ull accp[8][8];
#pragma unroll
        for (int i = 0; i < 8; i++)
#pragma unroll
            for (int jj = 0; jj < 8; jj++) accp[i][jj] = 0ull;

        if (t > 0) {
            // prologue: stage tile 0 (k 0..31) into buffer 0
#pragma unroll
            for (int v = 0; v < 16; v++) {
                int f4 = tid + v * 256;
                int kk = f4 >> 7, c4 = f4 & 127;
                cp16(wsm_s + (kk * W_STR + c4 * 4) * 4,
                     g_whh_pT + (size_t)kk * 512 + c4 * 4);
            }
            cp_commit();

#pragma unroll 1
            for (int kt = 0; kt < 4; kt++) {
                if (kt < 3) {
                    unsigned db = wsm_s + (((kt + 1) & 1) * KT * W_STR) * 4;
#pragma unroll
                    for (int v = 0; v < 16; v++) {
                        int f4 = tid + v * 256;
                        int kk = f4 >> 7, c4 = f4 & 127;
                        cp16(db + (kk * W_STR + c4 * 4) * 4,
                             g_whh_pT + (size_t)((kt + 1) * KT + kk) * 512 + c4 * 4);
                    }
                    cp_commit();
                    cp_wait<1>();
                } else {
                    cp_wait<0>();
                }
                __syncthreads();

                const float* wb = wsm + (kt & 1) * KT * W_STR;
                const float* ub = u + kt * KT;
#pragma unroll 4
                for (int kk2 = 0; kk2 < KT / 2; kk2++) {
                    float2 uk[8];
#pragma unroll
                    for (int i = 0; i < 8; i++)
                        uk[i] = *(const float2*)(ub + (wrp * 8 + i) * U_STR + 2 * kk2);
#pragma unroll
                    for (int sub = 0; sub < 2; sub++) {
                        ull wvp[8];
#pragma unroll
                        for (int jj = 0; jj < 8; jj++) {
                            float2 w2 = *(const float2*)(wb + (2 * kk2 + sub) * W_STR + co[jj]);
                            wvp[jj] = pack2(w2.x, w2.y);
                        }
#pragma unroll
                        for (int i = 0; i < 8; i++) {
                            float us = sub ? uk[i].y : uk[i].x;
                            ull up = pack2(us, us);
#pragma unroll
                            for (int jj = 0; jj < 8; jj++)
                                accp[i][jj] = ffma2_(up, wvp[jj], accp[i][jj]);
                        }
                    }
                }
                __syncthreads();
            }
        }

        // x-contribution: acc = acc + bias + att * P2[src]  (batched 2 rows)
#pragma unroll
        for (int b = 0; b < 4; b++) {
            ull pvp[2][8];
#pragma unroll
            for (int i2 = 0; i2 < 2; i2++) {
                int s = ssrc[wrp * 8 + b * 2 + i2];
                const float* pp = g_P2 + (size_t)s * 512;
#pragma unroll
                for (int jj = 0; jj < 8; jj++) {
                    float2 v2 = *(const float2*)(pp + co[jj]);
                    pvp[i2][jj] = pack2(v2.x, v2.y);
                }
            }
#pragma unroll
            for (int i2 = 0; i2 < 2; i2++) {
                int i = b * 2 + i2;
                float a = satt[wrp * 8 + i];
                ull ap = pack2(a, a);
#pragma unroll
                for (int jj = 0; jj < 8; jj++)
                    accp[i][jj] = ffma2_(ap, pvp[i2][jj], add2_(accp[i][jj], bcp[jj]));
            }
        }

        // gate activations + c/h update (h written in place; all u reads done)
#pragma unroll
        for (int i = 0; i < 8; i++) {
#pragma unroll
            for (int cs = 0; cs < 2; cs++) {
                float2 iv = unpack2(accp[i][cs * 4 + 0]);
                float2 fv = unpack2(accp[i][cs * 4 + 1]);
                float2 gv = unpack2(accp[i][cs * 4 + 2]);
                float2 ov = unpack2(accp[i][cs * 4 + 3]);
                float2 cp2 = creg2[i][cs];
                float c0 = fmaf(sig_fast(fv.x), cp2.x, sig_fast(iv.x) * tanh_fast(gv.x));
                float c1 = fmaf(sig_fast(fv.y), cp2.y, sig_fast(iv.y) * tanh_fast(gv.y));
                creg2[i][cs] = make_float2(c0, c1);
                float2 hh = make_float2(sig_fast(ov.x) * tanh_fast(c0),
                                        sig_fast(ov.y) * tanh_fast(c1));
                *(float2*)(u + (wrp * 8 + i) * U_STR + (hl + 2 * cs) * 32 + 2 * p) = hh;
            }
        }
        __syncthreads();
    }

    // epilogue: final h in u
    for (int idx = tid; idx < 64 * 128; idx += 256) {
        int r = idx >> 7, d = idx & 127;
        int n = n0 + r;
        if (n < NN) {
            float v = u[r * U_STR + d] + out[(size_t)n * 128 + d] + bias[d];
            out[(size_t)n * 128 + d] = (v >= 0.0f) ? v : 0.01f * v;
        }
    }
}

// ---------------- launch ----------------
extern "C" void kernel_launch(void* const* d_in, const int* in_sizes, int n_in,
                              void* d_out, int out_size) {
    const float* x    = (const float*)d_in[0];
    const float* Wp   = (const float*)d_in[1];
    const float* asrc = (const float*)d_in[2];
    const float* atrg = (const float*)d_in[3];
    const float* Wsk  = (const float*)d_in[4];
    const float* bias = (const float*)d_in[5];
    // d_in[6..9]: forward-direction weights, unused by the reference
    const float* wihb = (const float*)d_in[10];
    const float* whhb = (const float*)d_in[11];
    const float* bihb = (const float*)d_in[12];
    const float* bhhb = (const float*)d_in[13];
    const int*   ei   = (const int*)d_in[14];
    float* out = (float*)d_out;

    (void)in_sizes; (void)n_in; (void)out_size;

    cudaFuncSetAttribute(lstm_k, cudaFuncAttributeMaxDynamicSharedMemorySize,
                         LSTM_SM_FLOATS * (int)sizeof(float));

    prep_w_k<<<256, 256>>>(wihb, whhb, bihb, bhhb);
    wcomb_k<<<512, 256>>>(Wp);
    vav_k<<<1, 256>>>(Wp, asrc, atrg);
    sdotsX_k<<<(NN * 32 + 255) / 256, 256>>>(x);
    {
        dim3 g((NN + 63) / 64, 2);
        p2x_k<<<g, 256>>>(x);
    }
    skip_k<<<(NN + 63) / 64, 256>>>(x, Wsk, out);
    initmax_k<<<1, 1>>>();
    scores_k<<<EE / 256, 256>>>(ei);
    sort_k<<<(NN + 255) / 256, 256>>>(ei);
    lstm_k<<<(NN + 63) / 64, 256, LSTM_SM_FLOATS * (int)sizeof(float)>>>(bias, out);
}

// round 12
// speedup vs baseline: 1.1247x; 1.0311x over previous
#include <cuda_runtime.h>
#include <math.h>

// ---------------- problem constants ----------------
#define NN    50000
#define FIN   256
#define FOUT  128
#define HH    128
#define DD    16
#define EE    (NN*DD)     // 800000
#define G4    512         // 4*H

// ---------------- scratch ----------------
__device__ float    g_proj[(size_t)NN*FOUT];   // 25.6MB
__device__ float    g_P2[(size_t)NN*G4];       // 102.4MB  P2 = proj @ w_ih^T (permuted cols)
__device__ float    g_ssrc[NN];
__device__ float    g_strg[NN];
__device__ int      g_seqsrc[EE];
__device__ float    g_seqatt[EE];
__device__ float    g_wih_p[G4*HH];            // permuted w_ih  [512 rows][128]
__device__ float    g_whh_pT[HH*G4];           // permuted w_hh  [128 k][512 cols] K-major
__device__ float    g_bcat[G4];

// ---------------- helpers ----------------
__device__ __forceinline__ float tanh_fast(float x) {
    float r;
    asm("tanh.approx.f32 %0, %1;" : "=f"(r) : "f"(x));
    return r;
}
__device__ __forceinline__ float sig_fast(float x) {
    return fmaf(tanh_fast(0.5f * x), 0.5f, 0.5f);
}
// packed f32x2 ops (Blackwell sm_103a)
typedef unsigned long long ull;
__device__ __forceinline__ ull pack2(float x, float y) {
    ull r; asm("mov.b64 %0, {%1,%2};" : "=l"(r) : "f"(x), "f"(y)); return r;
}
__device__ __forceinline__ float2 unpack2(ull v) {
    float2 r; asm("mov.b64 {%0,%1}, %2;" : "=f"(r.x), "=f"(r.y) : "l"(v)); return r;
}
__device__ __forceinline__ ull ffma2_(ull a, ull b, ull c) {
    ull d; asm("fma.rn.f32x2 %0, %1, %2, %3;" : "=l"(d) : "l"(a), "l"(b), "l"(c)); return d;
}
__device__ __forceinline__ ull add2_(ull a, ull b) {
    ull d; asm("add.rn.f32x2 %0, %1, %2;" : "=l"(d) : "l"(a), "l"(b)); return d;
}
// cp.async helpers
__device__ __forceinline__ void cp16(unsigned dst, const void* src) {
    asm volatile("cp.async.ca.shared.global [%0], [%1], 16;" :: "r"(dst), "l"(src));
}
__device__ __forceinline__ void cp_commit() { asm volatile("cp.async.commit_group;"); }
template <int N>
__device__ __forceinline__ void cp_wait() { asm volatile("cp.async.wait_group %0;" :: "n"(N)); }

// ---------------- kernel 1: prep + proj/skip GEMM + attention dots (fused) -------
// blocks 0..255 additionally build the permuted LSTM weights.
// GEMM: 64 rows x 256 cols (cols 0..127 -> g_proj, 128..255 -> d_out skip).
// Epilogue: s_src/s_trg dots from register-resident proj + warp reduction.
__global__ __launch_bounds__(256) void gemm1_k(const float* __restrict__ x,
                                               const float* __restrict__ Wp,
                                               const float* __restrict__ Wsk,
                                               const float* __restrict__ asrc,
                                               const float* __restrict__ atrg,
                                               const float* __restrict__ wih,
                                               const float* __restrict__ whh,
                                               const float* __restrict__ bih,
                                               const float* __restrict__ bhh,
                                               float* __restrict__ out) {
    __shared__ float xs2[32 * 66];    // [kk][row] transposed, pad 2
    __shared__ float ws[256 * 33];    // [col][kk]
    int tid = threadIdx.x, lane = tid & 31, wrp = tid >> 5;
    int n0 = blockIdx.x * 64;

    // fused weight prep (one idx per thread in blocks 0..255)
    if (blockIdx.x < 256) {
        int idx = blockIdx.x * 256 + tid;   // 0..65535
        int R = idx >> 7;
        int k = idx & 127;
        int ch = R >> 7, c = R & 127;
        int gate = c >> 5, dd = c & 31;
        int grow = gate * 128 + ch * 32 + dd;
        g_wih_p[R * 128 + k]  = wih[grow * 128 + k];
        g_whh_pT[k * 512 + R] = whh[grow * 128 + k];
        if (k == 0) g_bcat[R] = bih[grow] + bhh[grow];
    }

    ull accp[4][8];
#pragma unroll
    for (int rp = 0; rp < 4; rp++)
#pragma unroll
        for (int j = 0; j < 8; j++) accp[rp][j] = 0ull;

    for (int k0 = 0; k0 < 256; k0 += 32) {
        __syncthreads();
#pragma unroll
        for (int v = 0; v < 8; v++) {
            int idx = tid + v * 256;
            int r = idx >> 5, kk = idx & 31;
            int n = n0 + r;
            xs2[kk * 66 + r] = (n < NN) ? x[(size_t)n * 256 + k0 + kk] : 0.0f;
        }
#pragma unroll
        for (int v = 0; v < 32; v++) {
            int idx = tid + v * 256;
            int c = idx >> 5, kk = idx & 31;
            ws[c * 33 + kk] = (c < 128) ? Wp[c * 256 + k0 + kk]
                                        : Wsk[(c - 128) * 256 + k0 + kk];
        }
        __syncthreads();
#pragma unroll 4
        for (int kk = 0; kk < 32; kk++) {
            ull uvp[4], wvp[8];
#pragma unroll
            for (int rp = 0; rp < 4; rp++) {
                float2 u2 = *(const float2*)(xs2 + kk * 66 + wrp * 8 + 2 * rp);
                uvp[rp] = pack2(u2.x, u2.y);
            }
#pragma unroll
            for (int j = 0; j < 8; j++) {
                float wv = ws[(j * 32 + lane) * 33 + kk];
                wvp[j] = pack2(wv, wv);
            }
#pragma unroll
            for (int rp = 0; rp < 4; rp++)
#pragma unroll
                for (int j = 0; j < 8; j++)
                    accp[rp][j] = ffma2_(uvp[rp], wvp[j], accp[rp][j]);
        }
    }

    // store proj/skip
#pragma unroll
    for (int rp = 0; rp < 4; rp++) {
        int n = n0 + wrp * 8 + 2 * rp;
#pragma unroll
        for (int j = 0; j < 8; j++) {
            float2 res = unpack2(accp[rp][j]);
            int c = j * 32 + lane;
            if (n < NN) {
                if (c < 128) g_proj[(size_t)n * 128 + c] = res.x;
                else         out[(size_t)n * 128 + (c - 128)] = res.x;
            }
            if (n + 1 < NN) {
                if (c < 128) g_proj[(size_t)(n + 1) * 128 + c] = res.y;
                else         out[(size_t)(n + 1) * 128 + (c - 128)] = res.y;
            }
        }
    }

    // fused attention dots: s_src/s_trg for the 8 rows (4 packed row-pairs)
    ull s1p[4], s2p[4];
#pragma unroll
    for (int rp = 0; rp < 4; rp++) { s1p[rp] = 0ull; s2p[rp] = 0ull; }
#pragma unroll
    for (int j = 0; j < 4; j++) {            // proj cols only (j*32+lane < 128)
        int c = j * 32 + lane;
        float av = asrc[c], tv = atrg[c];
        ull avp = pack2(av, av);
        ull tvp = pack2(tv, tv);
#pragma unroll
        for (int rp = 0; rp < 4; rp++) {
            s1p[rp] = ffma2_(accp[rp][j], avp, s1p[rp]);
            s2p[rp] = ffma2_(accp[rp][j], tvp, s2p[rp]);
        }
    }
#pragma unroll
    for (int rp = 0; rp < 4; rp++) {
#pragma unroll
        for (int o = 16; o; o >>= 1) {
            s1p[rp] = add2_(s1p[rp], __shfl_xor_sync(0xffffffffu, s1p[rp], o));
            s2p[rp] = add2_(s2p[rp], __shfl_xor_sync(0xffffffffu, s2p[rp], o));
        }
        if (lane == 0) {
            float2 v1 = unpack2(s1p[rp]);
            float2 v2 = unpack2(s2p[rp]);
            int n = n0 + wrp * 8 + 2 * rp;
            if (n < NN)     { g_ssrc[n] = v1.x;     g_strg[n] = v2.x; }
            if (n + 1 < NN) { g_ssrc[n + 1] = v1.y; g_strg[n + 1] = v2.y; }
        }
    }
}

// ---------------- kernel 2: P2 = proj @ w_ih_p^T (FFMA2, row-paired, K=128) ------
__global__ __launch_bounds__(256) void p2_k() {
    __shared__ float xs2[32 * 66];
    __shared__ float ws[256 * 33];
    int tid = threadIdx.x, lane = tid & 31, wrp = tid >> 5;
    int n0 = blockIdx.x * 64;
    int coff = blockIdx.y * 256;
    ull accp[4][8];
#pragma unroll
    for (int rp = 0; rp < 4; rp++)
#pragma unroll
        for (int j = 0; j < 8; j++) accp[rp][j] = 0ull;

    for (int k0 = 0; k0 < 128; k0 += 32) {
        __syncthreads();
#pragma unroll
        for (int v = 0; v < 8; v++) {
            int idx = tid + v * 256;
            int r = idx >> 5, kk = idx & 31;
            int n = n0 + r;
            xs2[kk * 66 + r] = (n < NN) ? g_proj[(size_t)n * 128 + k0 + kk] : 0.0f;
        }
#pragma unroll
        for (int v = 0; v < 32; v++) {
            int idx = tid + v * 256;
            int c = idx >> 5, kk = idx & 31;
            ws[c * 33 + kk] = g_wih_p[(coff + c) * 128 + k0 + kk];
        }
        __syncthreads();
#pragma unroll 4
        for (int kk = 0; kk < 32; kk++) {
            ull uvp[4], wvp[8];
#pragma unroll
            for (int rp = 0; rp < 4; rp++) {
                float2 u2 = *(const float2*)(xs2 + kk * 66 + wrp * 8 + 2 * rp);
                uvp[rp] = pack2(u2.x, u2.y);
            }
#pragma unroll
            for (int j = 0; j < 8; j++) {
                float wv = ws[(j * 32 + lane) * 33 + kk];
                wvp[j] = pack2(wv, wv);
            }
#pragma unroll
            for (int rp = 0; rp < 4; rp++)
#pragma unroll
                for (int j = 0; j < 8; j++)
                    accp[rp][j] = ffma2_(uvp[rp], wvp[j], accp[rp][j]);
        }
    }
#pragma unroll
    for (int rp = 0; rp < 4; rp++) {
        int n = n0 + wrp * 8 + 2 * rp;
#pragma unroll
        for (int j = 0; j < 8; j++) {
            float2 res = unpack2(accp[rp][j]);
            int c = coff + j * 32 + lane;
            if (n < NN)     g_P2[(size_t)n * 512 + c] = res.x;
            if (n + 1 < NN) g_P2[(size_t)(n + 1) * 512 + c] = res.y;
        }
    }
}

// ---------------- kernel 3: fused scores + softmax (per-node max) + sort ---------
// softmax is shift-invariant, so per-node max subtraction yields identical
// attention to the reference's global-max version (denom >= 1 makes 1e-16 moot).
__global__ void sortf_k(const int* __restrict__ ei) {
    int n = blockIdx.x * blockDim.x + threadIdx.x;
    if (n >= NN) return;
    int srcs[DD];
    float ev[DD], srt[DD];
    int idx[DD];
    float mx = -1e30f;
#pragma unroll
    for (int j = 0; j < DD; j++) {
        int e = n * DD + j;
        int s = ei[e];
        int t = ei[EE + e];
        srcs[j] = s;
        float v = g_ssrc[s] + g_strg[t];
        v = (v >= 0.0f) ? v : 0.2f * v;
        ev[j] = v;
        mx = fmaxf(mx, v);
    }
    float denom = 0.0f;
#pragma unroll
    for (int j = 0; j < DD; j++) {
        float e = expf(ev[j] - mx);
        ev[j] = e;
        denom += e;
    }
    denom += 1e-16f;
    // insertion sort, descending; "<=" shift => later (larger) original index
    // first on ties, matching stable-ascending argsort + reversal.
    for (int j = 0; j < DD; j++) {
        float key = ev[j];
        int pos = j;
        while (pos > 0 && srt[pos - 1] <= key) {
            srt[pos] = srt[pos - 1];
            idx[pos] = idx[pos - 1];
            pos--;
        }
        srt[pos] = key;
        idx[pos] = j;
    }
    float inv = 1.0f / denom;
#pragma unroll
    for (int t = 0; t < DD; t++) {
        g_seqsrc[n * DD + t] = srcs[idx[t]];
        g_seqatt[n * DD + t] = srt[t] * inv;
    }
}

// ---------------- kernel 4: backward LSTM (R7 schedule — proven fastest) ---------
// 64 nodes / block, 256 threads (8 warps). Warp owns 8 rows; lane (hl=lane>>4,
// p=lane&15) owns hidden-dim pairs {2p,2p+1} of chunks (hl) and (hl+2).
// One GEMM pass per timestep over all 512 gate cols; h in place; c in registers.
#define U_STR 132
#define KT 32
#define W_STR 520
#define LSTM_SM_FLOATS (64*U_STR + 2*KT*W_STR + 160)

__global__ __launch_bounds__(256, 1) void lstm_k(const float* __restrict__ bias,
                                                 float* __restrict__ out) {
    extern __shared__ float sm[];
    float* u    = sm;                          // [64][U_STR] h (in-place)
    float* wsm  = sm + 64 * U_STR;             // [2][KT][W_STR] w tiles
    float* satt = wsm + 2 * KT * W_STR;        // [64]
    int*   ssrc = (int*)(satt + 64);           // [64]

    int tid = threadIdx.x, lane = tid & 31, wrp = tid >> 5;
    int hl = lane >> 4, p = lane & 15;
    int n0 = blockIdx.x * 64;
    unsigned wsm_s = (unsigned)__cvta_generic_to_shared(wsm);

    // col offsets: jj = cs*4 + g -> col = (hl+2cs)*128 + g*32 + 2p
    int co[8];
#pragma unroll
    for (int jj = 0; jj < 8; jj++)
        co[jj] = (hl + 2 * (jj >> 2)) * 128 + (jj & 3) * 32 + 2 * p;

    // bias pairs
    ull bcp[8];
#pragma unroll
    for (int jj = 0; jj < 8; jj++) {
        float2 b2 = *(const float2*)(g_bcat + co[jj]);
        bcp[jj] = pack2(b2.x, b2.y);
    }

    // cell state: creg2[row][cs] = c for dims (hl+2cs)*32 + {2p,2p+1}
    float2 creg2[8][2];
#pragma unroll
    for (int i = 0; i < 8; i++)
#pragma unroll
        for (int cs = 0; cs < 2; cs++) creg2[i][cs] = make_float2(0.0f, 0.0f);

#pragma unroll 1
    for (int t = 0; t < DD; t++) {
        if (tid < 64) {
            int n = n0 + tid;
            if (n < NN) {
                ssrc[tid] = g_seqsrc[n * DD + t];
                satt[tid] = g_seqatt[n * DD + t];
            } else {
                ssrc[tid] = 0;
                satt[tid] = 0.0f;
            }
        }
        __syncthreads();

        ull accp[8][8];
#pragma unroll
        for (int i = 0; i < 8; i++)
#pragma unroll
            for (int jj = 0; jj < 8; jj++) accp[i][jj] = 0ull;

        if (t > 0) {
            // prologue: stage tile 0 (k 0..31) into buffer 0
#pragma unroll
            for (int v = 0; v < 16; v++) {
                int f4 = tid + v * 256;
                int kk = f4 >> 7, c4 = f4 & 127;
                cp16(wsm_s + (kk * W_STR + c4 * 4) * 4,
                     g_whh_pT + (size_t)kk * 512 + c4 * 4);
            }
            cp_commit();

#pragma unroll 1
            for (int kt = 0; kt < 4; kt++) {
                if (kt < 3) {
                    unsigned db = wsm_s + (((kt + 1) & 1) * KT * W_STR) * 4;
#pragma unroll
                    for (int v = 0; v < 16; v++) {
                        int f4 = tid + v * 256;
                        int kk = f4 >> 7, c4 = f4 & 127;
                        cp16(db + (kk * W_STR + c4 * 4) * 4,
                             g_whh_pT + (size_t)((kt + 1) * KT + kk) * 512 + c4 * 4);
                    }
                    cp_commit();
                    cp_wait<1>();
                } else {
                    cp_wait<0>();
                }
                __syncthreads();

                const float* wb = wsm + (kt & 1) * KT * W_STR;
                const float* ub = u + kt * KT;
#pragma unroll 4
                for (int kk2 = 0; kk2 < KT / 2; kk2++) {
                    float2 uk[8];
#pragma unroll
                    for (int i = 0; i < 8; i++)
                        uk[i] = *(const float2*)(ub + (wrp * 8 + i) * U_STR + 2 * kk2);
#pragma unroll
                    for (int sub = 0; sub < 2; sub++) {
                        ull wvp[8];
#pragma unroll
                        for (int jj = 0; jj < 8; jj++) {
                            float2 w2 = *(const float2*)(wb + (2 * kk2 + sub) * W_STR + co[jj]);
                            wvp[jj] = pack2(w2.x, w2.y);
                        }
#pragma unroll
                        for (int i = 0; i < 8; i++) {
                            float us = sub ? uk[i].y : uk[i].x;
                            ull up = pack2(us, us);
#pragma unroll
                            for (int jj = 0; jj < 8; jj++)
                                accp[i][jj] = ffma2_(up, wvp[jj], accp[i][jj]);
                        }
                    }
                }
                __syncthreads();
            }
        }

        // x-contribution: acc = acc + bias + att * P2[src]  (batched 2 rows)
#pragma unroll
        for (int b = 0; b < 4; b++) {
            ull pvp[2][8];
#pragma unroll
            for (int i2 = 0; i2 < 2; i2++) {
                int s = ssrc[wrp * 8 + b * 2 + i2];
                const float* pp = g_P2 + (size_t)s * 512;
#pragma unroll
                for (int jj = 0; jj < 8; jj++) {
                    float2 v2 = *(const float2*)(pp + co[jj]);
                    pvp[i2][jj] = pack2(v2.x, v2.y);
                }
            }
#pragma unroll
            for (int i2 = 0; i2 < 2; i2++) {
                int i = b * 2 + i2;
                float a = satt[wrp * 8 + i];
                ull ap = pack2(a, a);
#pragma unroll
                for (int jj = 0; jj < 8; jj++)
                    accp[i][jj] = ffma2_(ap, pvp[i2][jj], add2_(accp[i][jj], bcp[jj]));
            }
        }

        // gate activations + c/h update (h written in place; all u reads done)
#pragma unroll
        for (int i = 0; i < 8; i++) {
#pragma unroll
            for (int cs = 0; cs < 2; cs++) {
                float2 iv = unpack2(accp[i][cs * 4 + 0]);
                float2 fv = unpack2(accp[i][cs * 4 + 1]);
                float2 gv = unpack2(accp[i][cs * 4 + 2]);
                float2 ov = unpack2(accp[i][cs * 4 + 3]);
                float2 cp2 = creg2[i][cs];
                float c0 = fmaf(sig_fast(fv.x), cp2.x, sig_fast(iv.x) * tanh_fast(gv.x));
                float c1 = fmaf(sig_fast(fv.y), cp2.y, sig_fast(iv.y) * tanh_fast(gv.y));
                creg2[i][cs] = make_float2(c0, c1);
                float2 hh = make_float2(sig_fast(ov.x) * tanh_fast(c0),
                                        sig_fast(ov.y) * tanh_fast(c1));
                *(float2*)(u + (wrp * 8 + i) * U_STR + (hl + 2 * cs) * 32 + 2 * p) = hh;
            }
        }
        __syncthreads();
    }

    // epilogue: final h in u
    for (int idx = tid; idx < 64 * 128; idx += 256) {
        int r = idx >> 7, d = idx & 127;
        int n = n0 + r;
        if (n < NN) {
            float v = u[r * U_STR + d] + out[(size_t)n * 128 + d] + bias[d];
            out[(size_t)n * 128 + d] = (v >= 0.0f) ? v : 0.01f * v;
        }
    }
}

// ---------------- launch ----------------
extern "C" void kernel_launch(void* const* d_in, const int* in_sizes, int n_in,
                              void* d_out, int out_size) {
    const float* x    = (const float*)d_in[0];
    const float* Wp   = (const float*)d_in[1];
    const float* asrc = (const float*)d_in[2];
    const float* atrg = (const float*)d_in[3];
    const float* Wsk  = (const float*)d_in[4];
    const float* bias = (const float*)d_in[5];
    // d_in[6..9]: forward-direction weights, unused by the reference
    const float* wihb = (const float*)d_in[10];
    const float* whhb = (const float*)d_in[11];
    const float* bihb = (const float*)d_in[12];
    const float* bhhb = (const float*)d_in[13];
    const int*   ei   = (const int*)d_in[14];
    float* out = (float*)d_out;

    (void)in_sizes; (void)n_in; (void)out_size;

    cudaFuncSetAttribute(lstm_k, cudaFuncAttributeMaxDynamicSharedMemorySize,
                         LSTM_SM_FLOATS * (int)sizeof(float));

    gemm1_k<<<(NN + 63) / 64, 256>>>(x, Wp, Wsk, asrc, atrg,
                                     wihb, whhb, bihb, bhhb, out);
    {
        dim3 g((NN + 63) / 64, 2);
        p2_k<<<g, 256>>>();
    }
    sortf_k<<<(NN + 255) / 256, 256>>>(ei);
    lstm_k<<<(NN + 63) / 64, 256, LSTM_SM_FLOATS * (int)sizeof(float)>>>(bias, out);
}

// round 13
// speedup vs baseline: 1.1424x; 1.0158x over previous
#include <cuda_runtime.h>
#include <math.h>

// ---------------- problem constants ----------------
#define NN    50000
#define FIN   256
#define FOUT  128
#define HH    128
#define DD    16
#define EE    (NN*DD)     // 800000
#define G4    512         // 4*H

// ---------------- scratch ----------------
__device__ float    g_proj[(size_t)NN*FOUT];   // 25.6MB
__device__ float    g_P2[(size_t)NN*G4];       // 102.4MB  P2 = proj @ w_ih^T (permuted cols)
__device__ float    g_ssrc[NN];
__device__ float    g_strg[NN];
__device__ int      g_seqsrc[EE];
__device__ float    g_seqatt[EE];
__device__ float    g_wih_p[G4*HH];            // permuted w_ih  [512 rows][128]
__device__ float    g_whh_pT[HH*G4];           // permuted w_hh  [128 k][512 cols] K-major
__device__ float    g_bcat[G4];

// ---------------- helpers ----------------
__device__ __forceinline__ float tanh_fast(float x) {
    float r;
    asm("tanh.approx.f32 %0, %1;" : "=f"(r) : "f"(x));
    return r;
}
__device__ __forceinline__ float sig_fast(float x) {
    return fmaf(tanh_fast(0.5f * x), 0.5f, 0.5f);
}
// packed f32x2 ops (Blackwell sm_103a)
typedef unsigned long long ull;
__device__ __forceinline__ ull pack2(float x, float y) {
    ull r; asm("mov.b64 %0, {%1,%2};" : "=l"(r) : "f"(x), "f"(y)); return r;
}
__device__ __forceinline__ float2 unpack2(ull v) {
    float2 r; asm("mov.b64 {%0,%1}, %2;" : "=f"(r.x), "=f"(r.y) : "l"(v)); return r;
}
__device__ __forceinline__ ull ffma2_(ull a, ull b, ull c) {
    ull d; asm("fma.rn.f32x2 %0, %1, %2, %3;" : "=l"(d) : "l"(a), "l"(b), "l"(c)); return d;
}
__device__ __forceinline__ ull add2_(ull a, ull b) {
    ull d; asm("add.rn.f32x2 %0, %1, %2;" : "=l"(d) : "l"(a), "l"(b)); return d;
}
// cp.async helpers
__device__ __forceinline__ void cp16(unsigned dst, const void* src) {
    asm volatile("cp.async.ca.shared.global [%0], [%1], 16;" :: "r"(dst), "l"(src));
}
__device__ __forceinline__ void cp_commit() { asm volatile("cp.async.commit_group;"); }
template <int N>
__device__ __forceinline__ void cp_wait() { asm volatile("cp.async.wait_group %0;" :: "n"(N)); }

// ---------------- kernel 1: prep + proj/skip GEMM + attention dots (fused) -------
__global__ __launch_bounds__(256) void gemm1_k(const float* __restrict__ x,
                                               const float* __restrict__ Wp,
                                               const float* __restrict__ Wsk,
                                               const float* __restrict__ asrc,
                                               const float* __restrict__ atrg,
                                               const float* __restrict__ wih,
                                               const float* __restrict__ whh,
                                               const float* __restrict__ bih,
                                               const float* __restrict__ bhh,
                                               float* __restrict__ out) {
    __shared__ float xs2[32 * 66];    // [kk][row] transposed, pad 2
    __shared__ float ws[256 * 33];    // [col][kk]
    int tid = threadIdx.x, lane = tid & 31, wrp = tid >> 5;
    int n0 = blockIdx.x * 64;

    // fused weight prep (one idx per thread in blocks 0..255)
    if (blockIdx.x < 256) {
        int idx = blockIdx.x * 256 + tid;   // 0..65535
        int R = idx >> 7;
        int k = idx & 127;
        int ch = R >> 7, c = R & 127;
        int gate = c >> 5, dd = c & 31;
        int grow = gate * 128 + ch * 32 + dd;
        g_wih_p[R * 128 + k]  = wih[grow * 128 + k];
        g_whh_pT[k * 512 + R] = whh[grow * 128 + k];
        if (k == 0) g_bcat[R] = bih[grow] + bhh[grow];
    }

    ull accp[4][8];
#pragma unroll
    for (int rp = 0; rp < 4; rp++)
#pragma unroll
        for (int j = 0; j < 8; j++) accp[rp][j] = 0ull;

    for (int k0 = 0; k0 < 256; k0 += 32) {
        __syncthreads();
#pragma unroll
        for (int v = 0; v < 8; v++) {
            int idx = tid + v * 256;
            int r = idx >> 5, kk = idx & 31;
            int n = n0 + r;
            xs2[kk * 66 + r] = (n < NN) ? x[(size_t)n * 256 + k0 + kk] : 0.0f;
        }
#pragma unroll
        for (int v = 0; v < 32; v++) {
            int idx = tid + v * 256;
            int c = idx >> 5, kk = idx & 31;
            ws[c * 33 + kk] = (c < 128) ? Wp[c * 256 + k0 + kk]
                                        : Wsk[(c - 128) * 256 + k0 + kk];
        }
        __syncthreads();
#pragma unroll 4
        for (int kk = 0; kk < 32; kk++) {
            ull uvp[4], wvp[8];
#pragma unroll
            for (int rp = 0; rp < 4; rp++) {
                float2 u2 = *(const float2*)(xs2 + kk * 66 + wrp * 8 + 2 * rp);
                uvp[rp] = pack2(u2.x, u2.y);
            }
#pragma unroll
            for (int j = 0; j < 8; j++) {
                float wv = ws[(j * 32 + lane) * 33 + kk];
                wvp[j] = pack2(wv, wv);
            }
#pragma unroll
            for (int rp = 0; rp < 4; rp++)
#pragma unroll
                for (int j = 0; j < 8; j++)
                    accp[rp][j] = ffma2_(uvp[rp], wvp[j], accp[rp][j]);
        }
    }

    // store proj/skip
#pragma unroll
    for (int rp = 0; rp < 4; rp++) {
        int n = n0 + wrp * 8 + 2 * rp;
#pragma unroll
        for (int j = 0; j < 8; j++) {
            float2 res = unpack2(accp[rp][j]);
            int c = j * 32 + lane;
            if (n < NN) {
                if (c < 128) g_proj[(size_t)n * 128 + c] = res.x;
                else         out[(size_t)n * 128 + (c - 128)] = res.x;
            }
            if (n + 1 < NN) {
                if (c < 128) g_proj[(size_t)(n + 1) * 128 + c] = res.y;
                else         out[(size_t)(n + 1) * 128 + (c - 128)] = res.y;
            }
        }
    }

    // fused attention dots: s_src/s_trg for the 8 rows (4 packed row-pairs)
    ull s1p[4], s2p[4];
#pragma unroll
    for (int rp = 0; rp < 4; rp++) { s1p[rp] = 0ull; s2p[rp] = 0ull; }
#pragma unroll
    for (int j = 0; j < 4; j++) {            // proj cols only (j*32+lane < 128)
        int c = j * 32 + lane;
        float av = asrc[c], tv = atrg[c];
        ull avp = pack2(av, av);
        ull tvp = pack2(tv, tv);
#pragma unroll
        for (int rp = 0; rp < 4; rp++) {
            s1p[rp] = ffma2_(accp[rp][j], avp, s1p[rp]);
            s2p[rp] = ffma2_(accp[rp][j], tvp, s2p[rp]);
        }
    }
#pragma unroll
    for (int rp = 0; rp < 4; rp++) {
#pragma unroll
        for (int o = 16; o; o >>= 1) {
            s1p[rp] = add2_(s1p[rp], __shfl_xor_sync(0xffffffffu, s1p[rp], o));
            s2p[rp] = add2_(s2p[rp], __shfl_xor_sync(0xffffffffu, s2p[rp], o));
        }
        if (lane == 0) {
            float2 v1 = unpack2(s1p[rp]);
            float2 v2 = unpack2(s2p[rp]);
            int n = n0 + wrp * 8 + 2 * rp;
            if (n < NN)     { g_ssrc[n] = v1.x;     g_strg[n] = v2.x; }
            if (n + 1 < NN) { g_ssrc[n + 1] = v1.y; g_strg[n + 1] = v2.y; }
        }
    }
}

// ---------------- kernel 2: P2 = proj @ w_ih_p^T (FFMA2, row-paired, K=128) ------
__global__ __launch_bounds__(256) void p2_k() {
    __shared__ float xs2[32 * 66];
    __shared__ float ws[256 * 33];
    int tid = threadIdx.x, lane = tid & 31, wrp = tid >> 5;
    int n0 = blockIdx.x * 64;
    int coff = blockIdx.y * 256;
    ull accp[4][8];
#pragma unroll
    for (int rp = 0; rp < 4; rp++)
#pragma unroll
        for (int j = 0; j < 8; j++) accp[rp][j] = 0ull;

    for (int k0 = 0; k0 < 128; k0 += 32) {
        __syncthreads();
#pragma unroll
        for (int v = 0; v < 8; v++) {
            int idx = tid + v * 256;
            int r = idx >> 5, kk = idx & 31;
            int n = n0 + r;
            xs2[kk * 66 + r] = (n < NN) ? g_proj[(size_t)n * 128 + k0 + kk] : 0.0f;
        }
#pragma unroll
        for (int v = 0; v < 32; v++) {
            int idx = tid + v * 256;
            int c = idx >> 5, kk = idx & 31;
            ws[c * 33 + kk] = g_wih_p[(coff + c) * 128 + k0 + kk];
        }
        __syncthreads();
#pragma unroll 4
        for (int kk = 0; kk < 32; kk++) {
            ull uvp[4], wvp[8];
#pragma unroll
            for (int rp = 0; rp < 4; rp++) {
                float2 u2 = *(const float2*)(xs2 + kk * 66 + wrp * 8 + 2 * rp);
                uvp[rp] = pack2(u2.x, u2.y);
            }
#pragma unroll
            for (int j = 0; j < 8; j++) {
                float wv = ws[(j * 32 + lane) * 33 + kk];
                wvp[j] = pack2(wv, wv);
            }
#pragma unroll
            for (int rp = 0; rp < 4; rp++)
#pragma unroll
                for (int j = 0; j < 8; j++)
                    accp[rp][j] = ffma2_(uvp[rp], wvp[j], accp[rp][j]);
        }
    }
#pragma unroll
    for (int rp = 0; rp < 4; rp++) {
        int n = n0 + wrp * 8 + 2 * rp;
#pragma unroll
        for (int j = 0; j < 8; j++) {
            float2 res = unpack2(accp[rp][j]);
            int c = coff + j * 32 + lane;
            if (n < NN)     g_P2[(size_t)n * 512 + c] = res.x;
            if (n + 1 < NN) g_P2[(size_t)(n + 1) * 512 + c] = res.y;
        }
    }
}

// ---------------- kernel 3: fused scores + softmax (per-node max) + sort ---------
__global__ void sortf_k(const int* __restrict__ ei) {
    int n = blockIdx.x * blockDim.x + threadIdx.x;
    if (n >= NN) return;
    int srcs[DD];
    float ev[DD], srt[DD];
    int idx[DD];
    float mx = -1e30f;
#pragma unroll
    for (int j = 0; j < DD; j++) {
        int e = n * DD + j;
        int s = ei[e];
        int t = ei[EE + e];
        srcs[j] = s;
        float v = g_ssrc[s] + g_strg[t];
        v = (v >= 0.0f) ? v : 0.2f * v;
        ev[j] = v;
        mx = fmaxf(mx, v);
    }
    float denom = 0.0f;
#pragma unroll
    for (int j = 0; j < DD; j++) {
        float e = expf(ev[j] - mx);
        ev[j] = e;
        denom += e;
    }
    denom += 1e-16f;
    for (int j = 0; j < DD; j++) {
        float key = ev[j];
        int pos = j;
        while (pos > 0 && srt[pos - 1] <= key) {
            srt[pos] = srt[pos - 1];
            idx[pos] = idx[pos - 1];
            pos--;
        }
        srt[pos] = key;
        idx[pos] = j;
    }
    float inv = 1.0f / denom;
#pragma unroll
    for (int t = 0; t < DD; t++) {
        g_seqsrc[n * DD + t] = srcs[idx[t]];
        g_seqatt[n * DD + t] = srt[t] * inv;
    }
}

// ---------------- kernel 4: backward LSTM, continuous weight pipeline ------------
// R7 GEMM schedule. New: (a) w_hh tiles flow through a persistent 2-buffer ring
// across timesteps (tile needed 2 phases later is issued right after a buffer
// frees), killing the per-timestep cp_wait bubble; (b) all 16 timesteps of
// seqsrc/seqatt preloaded into SMEM once.
#define U_STR 132
#define KT 32
#define W_STR 520
#define LSTM_SM_FLOATS (64*U_STR + 2*KT*W_STR + 2*64*DD + 32)

__global__ __launch_bounds__(256, 1) void lstm_k(const float* __restrict__ bias,
                                                 float* __restrict__ out) {
    extern __shared__ float sm[];
    float* u    = sm;                          // [64][U_STR] h (in-place)
    float* wsm  = sm + 64 * U_STR;             // [2][KT][W_STR] w tile ring
    float* satt = wsm + 2 * KT * W_STR;        // [DD][64]
    int*   ssrc = (int*)(satt + 64 * DD);      // [DD][64]

    int tid = threadIdx.x, lane = tid & 31, wrp = tid >> 5;
    int hl = lane >> 4, p = lane & 15;
    int n0 = blockIdx.x * 64;
    unsigned wsm_s = (unsigned)__cvta_generic_to_shared(wsm);

    // col offsets: jj = cs*4 + g -> col = (hl+2cs)*128 + g*32 + 2p
    int co[8];
#pragma unroll
    for (int jj = 0; jj < 8; jj++)
        co[jj] = (hl + 2 * (jj >> 2)) * 128 + (jj & 3) * 32 + 2 * p;

    // bias pairs
    ull bcp[8];
#pragma unroll
    for (int jj = 0; jj < 8; jj++) {
        float2 b2 = *(const float2*)(g_bcat + co[jj]);
        bcp[jj] = pack2(b2.x, b2.y);
    }

    // cell state: creg2[row][cs] = c for dims (hl+2cs)*32 + {2p,2p+1}
    float2 creg2[8][2];
#pragma unroll
    for (int i = 0; i < 8; i++)
#pragma unroll
        for (int cs = 0; cs < 2; cs++) creg2[i][cs] = make_float2(0.0f, 0.0f);

    // preload ALL timesteps' seq data: layout [t][node]
#pragma unroll
    for (int v = 0; v < 4; v++) {
        int idx = tid + v * 256;             // 0..1023 = node*16 + t
        int node = idx >> 4, t = idx & 15;
        int n = n0 + node;
        if (n < NN) {
            ssrc[t * 64 + node] = g_seqsrc[n * DD + t];
            satt[t * 64 + node] = g_seqatt[n * DD + t];
        } else {
            ssrc[t * 64 + node] = 0;
            satt[t * 64 + node] = 0.0f;
        }
    }

    // weight ring prologue: issue tiles 0 and 1 (own commit groups)
#pragma unroll
    for (int tile = 0; tile < 2; tile++) {
        unsigned db = wsm_s + ((tile & 1) * KT * W_STR) * 4;
#pragma unroll
        for (int v = 0; v < 16; v++) {
            int f4 = tid + v * 256;
            int kk = f4 >> 7, c4 = f4 & 127;
            cp16(db + (kk * W_STR + c4 * 4) * 4,
                 g_whh_pT + (size_t)(tile * KT + kk) * 512 + c4 * 4);
        }
        cp_commit();
    }
    __syncthreads();   // seq data visible

#pragma unroll 1
    for (int t = 0; t < DD; t++) {
        ull accp[8][8];
#pragma unroll
        for (int i = 0; i < 8; i++)
#pragma unroll
            for (int jj = 0; jj < 8; jj++) accp[i][jj] = 0ull;

        if (t > 0) {
#pragma unroll 1
            for (int kt = 0; kt < 4; kt++) {
                cp_wait<1>();          // tile kt has landed (issued >=2 phases ago)
                __syncthreads();

                const float* wb = wsm + (kt & 1) * KT * W_STR;
                const float* ub = u + kt * KT;
#pragma unroll 4
                for (int kk2 = 0; kk2 < KT / 2; kk2++) {
                    float2 uk[8];
#pragma unroll
                    for (int i = 0; i < 8; i++)
                        uk[i] = *(const float2*)(ub + (wrp * 8 + i) * U_STR + 2 * kk2);
#pragma unroll
                    for (int sub = 0; sub < 2; sub++) {
                        ull wvp[8];
#pragma unroll
                        for (int jj = 0; jj < 8; jj++) {
                            float2 w2 = *(const float2*)(wb + (2 * kk2 + sub) * W_STR + co[jj]);
                            wvp[jj] = pack2(w2.x, w2.y);
                        }
#pragma unroll
                        for (int i = 0; i < 8; i++) {
                            float us = sub ? uk[i].y : uk[i].x;
                            ull up = pack2(us, us);
#pragma unroll
                            for (int jj = 0; jj < 8; jj++)
                                accp[i][jj] = ffma2_(up, wvp[jj], accp[i][jj]);
                        }
                    }
                }
                __syncthreads();

                // refill this buffer with the tile needed 2 phases from now
                {
                    int ntile = (kt + 2) & 3;
                    unsigned db = wsm_s + ((kt & 1) * KT * W_STR) * 4;
#pragma unroll
                    for (int v = 0; v < 16; v++) {
                        int f4 = tid + v * 256;
                        int kk = f4 >> 7, c4 = f4 & 127;
                        cp16(db + (kk * W_STR + c4 * 4) * 4,
                             g_whh_pT + (size_t)(ntile * KT + kk) * 512 + c4 * 4);
                    }
                    cp_commit();
                }
            }
        }

        // x-contribution: acc = acc + bias + att * P2[src]  (batched 2 rows)
        const float* sattT = satt + t * 64;
        const int*   ssrcT = ssrc + t * 64;
#pragma unroll
        for (int b = 0; b < 4; b++) {
            ull pvp[2][8];
#pragma unroll
            for (int i2 = 0; i2 < 2; i2++) {
                int s = ssrcT[wrp * 8 + b * 2 + i2];
                const float* pp = g_P2 + (size_t)s * 512;
#pragma unroll
                for (int jj = 0; jj < 8; jj++) {
                    float2 v2 = *(const float2*)(pp + co[jj]);
                    pvp[i2][jj] = pack2(v2.x, v2.y);
                }
            }
#pragma unroll
            for (int i2 = 0; i2 < 2; i2++) {
                int i = b * 2 + i2;
                float a = sattT[wrp * 8 + i];
                ull ap = pack2(a, a);
#pragma unroll
                for (int jj = 0; jj < 8; jj++)
                    accp[i][jj] = ffma2_(ap, pvp[i2][jj], add2_(accp[i][jj], bcp[jj]));
            }
        }

        // gate activations + c/h update (h written in place; all u reads done)
#pragma unroll
        for (int i = 0; i < 8; i++) {
#pragma unroll
            for (int cs = 0; cs < 2; cs++) {
                float2 iv = unpack2(accp[i][cs * 4 + 0]);
                float2 fv = unpack2(accp[i][cs * 4 + 1]);
                float2 gv = unpack2(accp[i][cs * 4 + 2]);
                float2 ov = unpack2(accp[i][cs * 4 + 3]);
                float2 cp2 = creg2[i][cs];
                float c0 = fmaf(sig_fast(fv.x), cp2.x, sig_fast(iv.x) * tanh_fast(gv.x));
                float c1 = fmaf(sig_fast(fv.y), cp2.y, sig_fast(iv.y) * tanh_fast(gv.y));
                creg2[i][cs] = make_float2(c0, c1);
                float2 hh = make_float2(sig_fast(ov.x) * tanh_fast(c0),
                                        sig_fast(ov.y) * tanh_fast(c1));
                *(float2*)(u + (wrp * 8 + i) * U_STR + (hl + 2 * cs) * 32 + 2 * p) = hh;
            }
        }
        __syncthreads();
    }

    // epilogue: final h in u
    for (int idx = tid; idx < 64 * 128; idx += 256) {
        int r = idx >> 7, d = idx & 127;
        int n = n0 + r;
        if (n < NN) {
            float v = u[r * U_STR + d] + out[(size_t)n * 128 + d] + bias[d];
            out[(size_t)n * 128 + d] = (v >= 0.0f) ? v : 0.01f * v;
        }
    }
}

// ---------------- launch ----------------
extern "C" void kernel_launch(void* const* d_in, const int* in_sizes, int n_in,
                              void* d_out, int out_size) {
    const float* x    = (const float*)d_in[0];
    const float* Wp   = (const float*)d_in[1];
    const float* asrc = (const float*)d_in[2];
    const float* atrg = (const float*)d_in[3];
    const float* Wsk  = (const float*)d_in[4];
    const float* bias = (const float*)d_in[5];
    // d_in[6..9]: forward-direction weights, unused by the reference
    const float* wihb = (const float*)d_in[10];
    const float* whhb = (const float*)d_in[11];
    const float* bihb = (const float*)d_in[12];
    const float* bhhb = (const float*)d_in[13];
    const int*   ei   = (const int*)d_in[14];
    float* out = (float*)d_out;

    (void)in_sizes; (void)n_in; (void)out_size;

    cudaFuncSetAttribute(lstm_k, cudaFuncAttributeMaxDynamicSharedMemorySize,
                         LSTM_SM_FLOATS * (int)sizeof(float));

    gemm1_k<<<(NN + 63) / 64, 256>>>(x, Wp, Wsk, asrc, atrg,
                                     wihb, whhb, bihb, bhhb, out);
    {
        dim3 g((NN + 63) / 64, 2);
        p2_k<<<g, 256>>>();
    }
    sortf_k<<<(NN + 255) / 256, 256>>>(ei);
    lstm_k<<<(NN + 63) / 64, 256, LSTM_SM_FLOATS * (int)sizeof(float)>>>(bias, out);
}